// round 1
// baseline (speedup 1.0000x reference)
#include <cuda_runtime.h>
#include <cuda_bf16.h>
#include <stdint.h>

// Problem constants (fixed by the dataset)
#define NN 50000
#define EE 600000
#define DD 128
#define HH 128
#define CC 40
#define LL 3
#define EPS 1e-5f

// ---------------- scratch (static __device__, no allocation) ----------------
__device__ float g_hc[NN * HH];   // x @ Wconv[i]
__device__ float g_hl[NN * HH];   // x @ Wlin[i]
__device__ float g_x [NN * HH];   // current layer activations
__device__ float g_xf[NN * HH];   // JK sum
__device__ float g_dinv[NN];
__device__ int   g_cnt[NN];
__device__ int   g_cur[NN];
__device__ int   g_off[NN + 1];
__device__ int   g_part[128];
__device__ int   g_srcs[EE];
__device__ float g_wsc[EE];       // dinv[src] for the sorted edge

// ---------------- f32x2 helpers ----------------
__device__ __forceinline__ unsigned long long pk2(float lo, float hi) {
    unsigned long long r;
    asm("mov.b64 %0, {%1, %2};" : "=l"(r) : "f"(lo), "f"(hi));
    return r;
}
__device__ __forceinline__ void up2(float &lo, float &hi, unsigned long long v) {
    asm("mov.b64 {%0, %1}, %2;" : "=f"(lo), "=f"(hi) : "l"(v));
}
__device__ __forceinline__ void f2fma(unsigned long long &d,
                                      unsigned long long a,
                                      unsigned long long b) {
    asm("fma.rn.f32x2 %0, %1, %2, %0;" : "+l"(d) : "l"(a), "l"(b));
}

__device__ __forceinline__ float wredsum(float v) {
    #pragma unroll
    for (int o = 16; o > 0; o >>= 1) v += __shfl_xor_sync(0xffffffffu, v, o);
    return v;
}

// ---------------- preprocessing ----------------
__global__ void k_zero(int n) {
    int i = blockIdx.x * blockDim.x + threadIdx.x;
    if (i < n) { g_cnt[i] = 0; g_cur[i] = 0; }
}

__global__ void k_deg(const int* __restrict__ ei, int e) {
    int i = blockIdx.x * blockDim.x + threadIdx.x;
    if (i < e) atomicAdd(&g_cnt[ei[e + i]], 1);   // dst row of edge_index
}

__global__ void k_dinv(int n) {
    int i = blockIdx.x * blockDim.x + threadIdx.x;
    if (i < n) g_dinv[i] = rsqrtf((float)g_cnt[i] + 1.0f);
}

__global__ void k_scan1(int n) {
    __shared__ int s[1024];
    int t = threadIdx.x;
    int idx = blockIdx.x * 1024 + t;
    int val = (idx < n) ? g_cnt[idx] : 0;
    s[t] = val;
    __syncthreads();
    #pragma unroll
    for (int o = 1; o < 1024; o <<= 1) {
        int x = (t >= o) ? s[t - o] : 0;
        __syncthreads();
        s[t] += x;
        __syncthreads();
    }
    if (idx < n) g_off[idx] = s[t] - val;   // exclusive
    if (t == 1023) g_part[blockIdx.x] = s[t];
}

__global__ void k_scan2(int nb, int n) {
    if (threadIdx.x == 0 && blockIdx.x == 0) {
        int run = 0;
        for (int b = 0; b < nb; b++) { int tmp = g_part[b]; g_part[b] = run; run += tmp; }
        g_off[n] = run;
    }
}

__global__ void k_scan3(int n) {
    int idx = blockIdx.x * 1024 + threadIdx.x;
    if (idx < n) g_off[idx] += g_part[blockIdx.x];
}

__global__ void k_place(const int* __restrict__ ei, int e) {
    int i = blockIdx.x * blockDim.x + threadIdx.x;
    if (i < e) {
        int s = ei[i];
        int d = ei[e + i];
        int p = g_off[d] + atomicAdd(&g_cur[d], 1);
        g_srcs[p] = s;
        g_wsc[p]  = g_dinv[s];
    }
}

// ---------------- fused GEMM: [hc | hl] = X @ [Wconv | Wlin] ----------------
// CTA: 64 rows x 256 cols, 256 threads, 8x8 outputs/thread via f32x2.
// Full W (128KB) + X tile (32KB) in smem.
#define GEMM_SMEM ((128 * 256 + 64 * 128) * 4)

__global__ void __launch_bounds__(256, 1)
k_gemm(const float* __restrict__ X, const float* __restrict__ Wc,
       const float* __restrict__ Wl, int nrows) {
    extern __shared__ float sm[];
    float* Ws = sm;              // [128][256]
    float* Xs = sm + 128 * 256;  // [64][128]
    int tid = threadIdx.x;
    int row0 = blockIdx.x * 64;

    const float4* Wc4 = (const float4*)Wc;
    const float4* Wl4 = (const float4*)Wl;
    float4* Ws4 = (float4*)Ws;
    #pragma unroll
    for (int t = tid; t < 128 * 32; t += 256) {
        int k = t >> 5, c = t & 31;
        Ws4[k * 64 + c]      = Wc4[t];
        Ws4[k * 64 + 32 + c] = Wl4[t];
    }
    const float4* X4 = (const float4*)X;
    float4* Xs4 = (float4*)Xs;
    #pragma unroll
    for (int t = tid; t < 64 * 32; t += 256) {
        int r = t >> 5, c = t & 31;
        int gr = row0 + r;
        float4 v = make_float4(0.f, 0.f, 0.f, 0.f);
        if (gr < nrows) v = X4[gr * 32 + c];
        Xs4[r * 32 + c] = v;
    }
    __syncthreads();

    int trow = tid >> 5, tcol = tid & 31;
    const float* XsB = Xs + (trow * 8) * 128;
    const float* WsB = Ws + tcol * 8;

    unsigned long long acc[8][4];
    #pragma unroll
    for (int i = 0; i < 8; i++)
        #pragma unroll
        for (int j = 0; j < 4; j++) acc[i][j] = 0ULL;

    #pragma unroll 2
    for (int kk = 0; kk < 128; kk += 4) {
        float4 a4[8];
        #pragma unroll
        for (int i = 0; i < 8; i++) a4[i] = *(const float4*)(XsB + i * 128 + kk);

        #define KSTEP(KU, COMP)                                              \
        {                                                                    \
            const float* wrow = WsB + (kk + KU) * 256;                       \
            float4 b0 = *(const float4*)(wrow);                              \
            float4 b1 = *(const float4*)(wrow + 4);                          \
            unsigned long long bp0 = pk2(b0.x, b0.y);                        \
            unsigned long long bp1 = pk2(b0.z, b0.w);                        \
            unsigned long long bp2 = pk2(b1.x, b1.y);                        \
            unsigned long long bp3 = pk2(b1.z, b1.w);                        \
            _Pragma("unroll")                                                \
            for (int i = 0; i < 8; i++) {                                    \
                unsigned long long ad = pk2(a4[i].COMP, a4[i].COMP);         \
                f2fma(acc[i][0], ad, bp0);                                   \
                f2fma(acc[i][1], ad, bp1);                                   \
                f2fma(acc[i][2], ad, bp2);                                   \
                f2fma(acc[i][3], ad, bp3);                                   \
            }                                                                \
        }
        KSTEP(0, x) KSTEP(1, y) KSTEP(2, z) KSTEP(3, w)
        #undef KSTEP
    }

    int n0 = tcol * 8;
    float* outp = (n0 < 128) ? g_hc : g_hl;
    int coff = (n0 < 128) ? n0 : (n0 - 128);
    #pragma unroll
    for (int i = 0; i < 8; i++) {
        int m = row0 + trow * 8 + i;
        if (m < nrows) {
            #pragma unroll
            for (int j = 0; j < 4; j++) {
                float lo, hi;
                up2(lo, hi, acc[i][j]);
                float2 v = make_float2(lo, hi);
                *(float2*)(outp + m * 128 + coff + 2 * j) = v;
            }
        }
    }
}

// ---------------- fused aggregate + bias + residual + LN + ReLU + JK --------
__global__ void __launch_bounds__(256)
k_agg(const float* __restrict__ bconv, const float* __restrict__ blin,
      const float* __restrict__ lng, const float* __restrict__ lnb,
      int layer, int n) {
    int gwarp = (blockIdx.x * blockDim.x + threadIdx.x) >> 5;
    if (gwarp >= n) return;
    int lane = threadIdx.x & 31;
    int node = gwarp;

    float dn = g_dinv[node];
    const float4* HC = (const float4*)g_hc;
    const float4* HL = (const float4*)g_hl;

    float4 acc = make_float4(0.f, 0.f, 0.f, 0.f);
    int b = g_off[node], e = g_off[node + 1];
    int i = b;
    for (; i + 2 <= e; i += 2) {
        int s0 = g_srcs[i], s1 = g_srcs[i + 1];
        float w0 = g_wsc[i] * dn, w1 = g_wsc[i + 1] * dn;
        float4 h0 = HC[s0 * 32 + lane];
        float4 h1 = HC[s1 * 32 + lane];
        acc.x += h0.x * w0 + h1.x * w1;
        acc.y += h0.y * w0 + h1.y * w1;
        acc.z += h0.z * w0 + h1.z * w1;
        acc.w += h0.w * w0 + h1.w * w1;
    }
    if (i < e) {
        int s0 = g_srcs[i];
        float w0 = g_wsc[i] * dn;
        float4 h0 = HC[s0 * 32 + lane];
        acc.x += h0.x * w0; acc.y += h0.y * w0;
        acc.z += h0.z * w0; acc.w += h0.w * w0;
    }
    // self loop
    float sd = dn * dn;
    float4 hs = HC[node * 32 + lane];
    acc.x += hs.x * sd; acc.y += hs.y * sd; acc.z += hs.z * sd; acc.w += hs.w * sd;

    float4 hl4 = HL[node * 32 + lane];
    float4 bc  = ((const float4*)bconv)[lane];
    float4 bl  = ((const float4*)blin)[lane];
    float v0 = acc.x + bc.x + hl4.x + bl.x;
    float v1 = acc.y + bc.y + hl4.y + bl.y;
    float v2 = acc.z + bc.z + hl4.z + bl.z;
    float v3 = acc.w + bc.w + hl4.w + bl.w;

    float mu = wredsum(v0 + v1 + v2 + v3) * (1.0f / 128.0f);
    float d0 = v0 - mu, d1 = v1 - mu, d2 = v2 - mu, d3 = v3 - mu;
    float var = wredsum(d0 * d0 + d1 * d1 + d2 * d2 + d3 * d3) * (1.0f / 128.0f);
    float inv = rsqrtf(var + EPS);

    float4 g4 = ((const float4*)lng)[lane];
    float4 b4 = ((const float4*)lnb)[lane];
    v0 = fmaxf(0.f, d0 * inv * g4.x + b4.x);
    v1 = fmaxf(0.f, d1 * inv * g4.y + b4.y);
    v2 = fmaxf(0.f, d2 * inv * g4.z + b4.z);
    v3 = fmaxf(0.f, d3 * inv * g4.w + b4.w);

    float4 out = make_float4(v0, v1, v2, v3);
    ((float4*)g_x)[node * 32 + lane] = out;
    float4* XF = (float4*)g_xf;
    if (layer == 0) {
        XF[node * 32 + lane] = out;
    } else {
        float4 r = XF[node * 32 + lane];
        r.x += v0; r.y += v1; r.z += v2; r.w += v3;
        XF[node * 32 + lane] = r;
    }
}

// ---------------- prediction GEMM: out[N,40] = xf @ Wpred + bpred -----------
// Block: 50 rows. thread (rg,cg): 2 rows x 4 cols via f32x2.
__global__ void __launch_bounds__(256)
k_pred(const float* __restrict__ Wp, const float* __restrict__ bp,
       float* __restrict__ out, int n) {
    __shared__ float xs[50 * 128];
    __shared__ float ws[128 * 40];
    int tid = threadIdx.x;
    int row0 = blockIdx.x * 50;

    for (int t = tid; t < 50 * 128; t += 256) {
        int r = t >> 7, c = t & 127;
        int gr = row0 + r;
        xs[t] = (gr < n) ? g_xf[gr * 128 + c] : 0.f;
    }
    for (int t = tid; t < 128 * 40; t += 256) ws[t] = Wp[t];
    __syncthreads();

    if (tid < 250) {
        int cg = tid % 10;          // col group: cols cg*4 .. cg*4+3
        int rg = tid / 10;          // rows 2*rg, 2*rg+1
        int r0 = 2 * rg, r1 = r0 + 1;
        unsigned long long a00 = 0ULL, a01 = 0ULL, a10 = 0ULL, a11 = 0ULL;
        #pragma unroll 4
        for (int k = 0; k < 128; k++) {
            float x0 = xs[r0 * 128 + k];
            float x1 = xs[r1 * 128 + k];
            float4 w4 = *(const float4*)&ws[k * 40 + cg * 4];
            unsigned long long wp0 = pk2(w4.x, w4.y);
            unsigned long long wp1 = pk2(w4.z, w4.w);
            unsigned long long ad0 = pk2(x0, x0);
            unsigned long long ad1 = pk2(x1, x1);
            f2fma(a00, ad0, wp0); f2fma(a01, ad0, wp1);
            f2fma(a10, ad1, wp0); f2fma(a11, ad1, wp1);
        }
        int c0 = cg * 4;
        float b0 = bp[c0], b1 = bp[c0 + 1], b2 = bp[c0 + 2], b3 = bp[c0 + 3];
        float lo, hi;
        int gr0 = row0 + r0, gr1 = row0 + r1;
        if (gr0 < n) {
            up2(lo, hi, a00);
            out[gr0 * 40 + c0]     = lo + b0;
            out[gr0 * 40 + c0 + 1] = hi + b1;
            up2(lo, hi, a01);
            out[gr0 * 40 + c0 + 2] = lo + b2;
            out[gr0 * 40 + c0 + 3] = hi + b3;
        }
        if (gr1 < n) {
            up2(lo, hi, a10);
            out[gr1 * 40 + c0]     = lo + b0;
            out[gr1 * 40 + c0 + 1] = hi + b1;
            up2(lo, hi, a11);
            out[gr1 * 40 + c0 + 2] = lo + b2;
            out[gr1 * 40 + c0 + 3] = hi + b3;
        }
    }
}

// ---------------- launch ----------------
extern "C" void kernel_launch(void* const* d_in, const int* in_sizes, int n_in,
                              void* d_out, int out_size) {
    const float* x      = (const float*)d_in[0];
    const int*   ei     = (const int*)  d_in[1];
    const float* Wconv  = (const float*)d_in[2];
    const float* bconv  = (const float*)d_in[3];
    const float* Wlin   = (const float*)d_in[4];
    const float* blin   = (const float*)d_in[5];
    const float* ln_g   = (const float*)d_in[6];
    const float* ln_b   = (const float*)d_in[7];
    const float* Wpred  = (const float*)d_in[8];
    const float* bpred  = (const float*)d_in[9];
    float* out = (float*)d_out;

    int n = in_sizes[0] / DD;     // 50000
    int e = in_sizes[1] / 2;      // 600000

    static bool attr_set = false;
    if (!attr_set) {
        cudaFuncSetAttribute(k_gemm, cudaFuncAttributeMaxDynamicSharedMemorySize,
                             GEMM_SMEM);
        attr_set = true;
    }

    int nb = (n + 1023) / 1024;

    k_zero<<<(n + 255) / 256, 256>>>(n);
    k_deg <<<(e + 255) / 256, 256>>>(ei, e);
    k_dinv<<<(n + 255) / 256, 256>>>(n);
    k_scan1<<<nb, 1024>>>(n);
    k_scan2<<<1, 32>>>(nb, n);
    k_scan3<<<nb, 1024>>>(n);
    k_place<<<(e + 255) / 256, 256>>>(ei, e);

    // layer pointer to current activations
    float* g_x_dev = nullptr;
    cudaGetSymbolAddress((void**)&g_x_dev, g_x);

    for (int i = 0; i < LL; i++) {
        const float* Xin = (i == 0) ? x : (const float*)g_x_dev;
        k_gemm<<<(n + 63) / 64, 256, GEMM_SMEM>>>(
            Xin, Wconv + i * DD * HH, Wlin + i * DD * HH, n);
        k_agg<<<(n + 7) / 8, 256>>>(bconv + i * HH, blin + i * HH,
                                    ln_g + i * HH, ln_b + i * HH, i, n);
    }

    k_pred<<<(n + 49) / 50, 256>>>(Wpred, bpred, out, n);
}

// round 5
// speedup vs baseline: 1.3169x; 1.3169x over previous
#include <cuda_runtime.h>
#include <cuda_bf16.h>
#include <stdint.h>

// Problem constants (fixed by the dataset)
#define NN 50000
#define EE 600000
#define DD 128
#define HH 128
#define CC 40
#define LL 3
#define EPS 1e-5f

#define SA 136            // padded smem row stride (elements) for A and B tiles
#define WIMG 17408        // 128 * 136 bf16 elements per W image

// ---------------- scratch (static __device__, no allocation) ----------------
__device__ float g_hc[NN * HH];   // x @ Wconv[i]
__device__ float g_hl[NN * HH];   // x @ Wlin[i]
__device__ float g_x [NN * HH];   // current layer activations
__device__ float g_xf[NN * HH];   // JK sum
__device__ float g_dinv[NN];
__device__ int   g_cnt[NN];
__device__ int   g_cur[NN];
__device__ int   g_off[NN + 1];
__device__ int   g_part[128];
__device__ int   g_srcs[EE];
__device__ float g_wsc[EE];
// Preformatted W: [layer][sel(conv/lin)][part(hi/lo)][128n x 136k] bf16
__device__ __nv_bfloat16 g_wb[LL * 2 * 2 * WIMG];

// ---------------- small PTX helpers ----------------
__device__ __forceinline__ uint32_t smem_u32(const void* p) {
    uint32_t a;
    asm("{ .reg .u64 t; cvta.to.shared.u64 t, %1; cvt.u32.u64 %0, t; }"
        : "=r"(a) : "l"(p));
    return a;
}
__device__ __forceinline__ void ldsm_x4(uint32_t* r, uint32_t addr) {
    asm volatile("ldmatrix.sync.aligned.m8n8.x4.shared.b16 {%0,%1,%2,%3}, [%4];"
        : "=r"(r[0]), "=r"(r[1]), "=r"(r[2]), "=r"(r[3]) : "r"(addr));
}
__device__ __forceinline__ void ldsm_x2(uint32_t* r, uint32_t addr) {
    asm volatile("ldmatrix.sync.aligned.m8n8.x2.shared.b16 {%0,%1}, [%2];"
        : "=r"(r[0]), "=r"(r[1]) : "r"(addr));
}
__device__ __forceinline__ void mma_bf16(float* c, const uint32_t* a,
                                         const uint32_t* b) {
    asm volatile("mma.sync.aligned.m16n8k16.row.col.f32.bf16.bf16.f32 "
                 "{%0,%1,%2,%3}, {%4,%5,%6,%7}, {%8,%9}, {%0,%1,%2,%3};"
                 : "+f"(c[0]), "+f"(c[1]), "+f"(c[2]), "+f"(c[3])
                 : "r"(a[0]), "r"(a[1]), "r"(a[2]), "r"(a[3]),
                   "r"(b[0]), "r"(b[1]));
}
__device__ __forceinline__ uint32_t pkbf(float a, float b) {
    __nv_bfloat162 t = __floats2bfloat162_rn(a, b);
    return *reinterpret_cast<uint32_t*>(&t);
}

// ---------------- f32x2 helpers (pred kernel) ----------------
__device__ __forceinline__ unsigned long long pk2(float lo, float hi) {
    unsigned long long r;
    asm("mov.b64 %0, {%1, %2};" : "=l"(r) : "f"(lo), "f"(hi));
    return r;
}
__device__ __forceinline__ void up2(float &lo, float &hi, unsigned long long v) {
    asm("mov.b64 {%0, %1}, %2;" : "=f"(lo), "=f"(hi) : "l"(v));
}
__device__ __forceinline__ void f2fma(unsigned long long &d,
                                      unsigned long long a,
                                      unsigned long long b) {
    asm("fma.rn.f32x2 %0, %1, %2, %0;" : "+l"(d) : "l"(a), "l"(b));
}
__device__ __forceinline__ float wredsum(float v) {
    #pragma unroll
    for (int o = 16; o > 0; o >>= 1) v += __shfl_xor_sync(0xffffffffu, v, o);
    return v;
}

// ---------------- preprocessing ----------------
__global__ void k_zero(int n) {
    int i = blockIdx.x * blockDim.x + threadIdx.x;
    if (i < n) { g_cnt[i] = 0; g_cur[i] = 0; }
}
__global__ void k_deg(const int* __restrict__ ei, int e) {
    int i = blockIdx.x * blockDim.x + threadIdx.x;
    if (i < e) atomicAdd(&g_cnt[ei[e + i]], 1);
}
__global__ void k_dinv(int n) {
    int i = blockIdx.x * blockDim.x + threadIdx.x;
    if (i < n) g_dinv[i] = rsqrtf((float)g_cnt[i] + 1.0f);
}
__global__ void k_scan1(int n) {
    __shared__ int s[1024];
    int t = threadIdx.x;
    int idx = blockIdx.x * 1024 + t;
    int val = (idx < n) ? g_cnt[idx] : 0;
    s[t] = val;
    __syncthreads();
    #pragma unroll
    for (int o = 1; o < 1024; o <<= 1) {
        int x = (t >= o) ? s[t - o] : 0;
        __syncthreads();
        s[t] += x;
        __syncthreads();
    }
    if (idx < n) g_off[idx] = s[t] - val;
    if (t == 1023) g_part[blockIdx.x] = s[t];
}
__global__ void k_scan2(int nb, int n) {
    if (threadIdx.x == 0 && blockIdx.x == 0) {
        int run = 0;
        for (int b = 0; b < nb; b++) { int tmp = g_part[b]; g_part[b] = run; run += tmp; }
        g_off[n] = run;
    }
}
__global__ void k_scan3(int n) {
    int idx = blockIdx.x * 1024 + threadIdx.x;
    if (idx < n) g_off[idx] += g_part[blockIdx.x];
}
__global__ void k_place(const int* __restrict__ ei, int e) {
    int i = blockIdx.x * blockDim.x + threadIdx.x;
    if (i < e) {
        int s = ei[i];
        int d = ei[e + i];
        int p = g_off[d] + atomicAdd(&g_cur[d], 1);
        g_srcs[p] = s;
        g_wsc[p]  = g_dinv[s];
    }
}

// ---------------- W preformat: fp32 -> bf16 hi/lo padded [n][k] images ------
__global__ void k_wprep(const float* __restrict__ Wconv,
                        const float* __restrict__ Wlin) {
    int i = blockIdx.x * blockDim.x + threadIdx.x;
    if (i >= LL * 128 * 128) return;
    int l = i >> 14;
    int k = (i >> 7) & 127;
    int n = i & 127;
    float c = Wconv[l * 16384 + k * 128 + n];
    float v = Wlin [l * 16384 + k * 128 + n];
    int pos = n * SA + k;
    __nv_bfloat16 ch = __float2bfloat16(c);
    __nv_bfloat16 cl = __float2bfloat16(c - __bfloat162float(ch));
    __nv_bfloat16 vh = __float2bfloat16(v);
    __nv_bfloat16 vl = __float2bfloat16(v - __bfloat162float(vh));
    __nv_bfloat16* base = g_wb + (size_t)l * 4 * WIMG;
    base[0 * WIMG + pos] = ch;   // conv hi
    base[1 * WIMG + pos] = cl;   // conv lo
    base[2 * WIMG + pos] = vh;   // lin hi
    base[3 * WIMG + pos] = vl;   // lin lo
}

// ---------------- tensor-core GEMM via mma.sync (bf16 3-term split) ---------
// CTA: 128 rows x 128 cols. blockIdx.y: 0 -> hc = X@Wconv, 1 -> hl = X@Wlin.
// smem: A_hi, A_lo, B_hi, B_lo each [128][136] bf16.
#define OFF_AH 0
#define OFF_AL (WIMG * 2)
#define OFF_BH (WIMG * 4)
#define OFF_BL (WIMG * 6)
#define MMA_SMEM (WIMG * 8)   // 139264 bytes

__global__ void __launch_bounds__(256, 1)
k_mma(const float* __restrict__ Xin, int layer, int nrows) {
    extern __shared__ char smc[];
    uint32_t sb = smem_u32(smc);
    int tid = threadIdx.x;
    int lane = tid & 31;
    int wid = tid >> 5;
    int row0 = blockIdx.x * 128;
    int sel = blockIdx.y;

    // ---- B copy: hi+lo images, contiguous 69632 B ----
    {
        const uint4* src = (const uint4*)(g_wb + ((size_t)layer * 2 + sel) * 2 * WIMG);
        uint4* dst = (uint4*)(smc + OFF_BH);
        #pragma unroll
        for (int t = tid; t < 4352; t += 256) dst[t] = src[t];
    }

    // ---- A convert: fp32 -> bf16 hi/lo into smem ----
    {
        int m  = tid >> 1;
        int kh = tid & 1;           // which 64-col half
        int gm = row0 + m;
        bool inb = (gm < nrows);
        // Clamp the source row so the address is always valid even if the
        // compiler hoists the loads above the predicate.
        int srow = inb ? gm : (nrows - 1);
        const float4* xr = (const float4*)Xin + (size_t)srow * 32 + kh * 16;
        uint32_t arow = (uint32_t)(m * SA + kh * 64) * 2;
        #pragma unroll
        for (int c4 = 0; c4 < 16; c4++) {
            float4 v = xr[c4];
            if (!inb) v = make_float4(0.f, 0.f, 0.f, 0.f);
            __nv_bfloat16 hx = __float2bfloat16(v.x);
            __nv_bfloat16 hy = __float2bfloat16(v.y);
            __nv_bfloat16 hz = __float2bfloat16(v.z);
            __nv_bfloat16 hw = __float2bfloat16(v.w);
            uint32_t hp0 = (uint32_t)__bfloat16_as_ushort(hx)
                         | ((uint32_t)__bfloat16_as_ushort(hy) << 16);
            uint32_t hp1 = (uint32_t)__bfloat16_as_ushort(hz)
                         | ((uint32_t)__bfloat16_as_ushort(hw) << 16);
            uint32_t lp0 = pkbf(v.x - __bfloat162float(hx),
                                v.y - __bfloat162float(hy));
            uint32_t lp1 = pkbf(v.z - __bfloat162float(hz),
                                v.w - __bfloat162float(hw));
            uint32_t off = arow + (uint32_t)c4 * 8;
            *(uint2*)(smc + OFF_AH + off) = make_uint2(hp0, hp1);
            *(uint2*)(smc + OFF_AL + off) = make_uint2(lp0, lp1);
        }
    }
    __syncthreads();

    // ---- MMA mainloop ----
    int wr = wid >> 1;            // warp row 0-3 (32 rows each)
    int wc = wid & 1;             // warp col 0-1 (64 cols each)

    int arow = wr * 32 + (lane & 7) + ((lane & 8) ? 8 : 0);
    int akof = (lane & 16) ? 8 : 0;
    uint32_t aH = sb + OFF_AH + (uint32_t)(arow * SA + akof) * 2;
    uint32_t aL = sb + OFF_AL + (uint32_t)(arow * SA + akof) * 2;

    int brow = wc * 64 + (lane & 7);
    int bkof = (lane & 8) ? 8 : 0;
    uint32_t bH = sb + OFF_BH + (uint32_t)(brow * SA + bkof) * 2;
    uint32_t bL = sb + OFF_BL + (uint32_t)(brow * SA + bkof) * 2;

    float c[2][8][4];
    #pragma unroll
    for (int i = 0; i < 2; i++)
        #pragma unroll
        for (int j = 0; j < 8; j++)
            #pragma unroll
            for (int q = 0; q < 4; q++) c[i][j][q] = 0.f;

    #pragma unroll
    for (int ks = 0; ks < 8; ks++) {
        uint32_t ka = ks * 32;    // 16 elements * 2 bytes
        uint32_t ah0[4], ah1[4], al0[4], al1[4];
        ldsm_x4(ah0, aH + ka);
        ldsm_x4(ah1, aH + ka + 16 * SA * 2);
        ldsm_x4(al0, aL + ka);
        ldsm_x4(al1, aL + ka + 16 * SA * 2);
        #pragma unroll
        for (int nt = 0; nt < 8; nt++) {
            uint32_t bh[2], bl[2];
            ldsm_x2(bh, bH + nt * (8 * SA * 2) + ka);
            ldsm_x2(bl, bL + nt * (8 * SA * 2) + ka);
            mma_bf16(c[0][nt], ah0, bh);
            mma_bf16(c[1][nt], ah1, bh);
            mma_bf16(c[0][nt], ah0, bl);
            mma_bf16(c[1][nt], ah1, bl);
            mma_bf16(c[0][nt], al0, bh);
            mma_bf16(c[1][nt], al1, bh);
        }
    }

    // ---- epilogue: write accumulators ----
    float* outp = sel ? g_hl : g_hc;
    int g  = lane >> 2;           // group id 0-7
    int tg = lane & 3;            // thread in group
    #pragma unroll
    for (int mt = 0; mt < 2; mt++) {
        int r0 = row0 + wr * 32 + mt * 16 + g;
        #pragma unroll
        for (int nt = 0; nt < 8; nt++) {
            int col = wc * 64 + nt * 8 + tg * 2;
            if (r0 < nrows)
                *(float2*)(outp + (size_t)r0 * 128 + col) =
                    make_float2(c[mt][nt][0], c[mt][nt][1]);
            if (r0 + 8 < nrows)
                *(float2*)(outp + (size_t)(r0 + 8) * 128 + col) =
                    make_float2(c[mt][nt][2], c[mt][nt][3]);
        }
    }
}

// ---------------- fused aggregate + bias + residual + LN + ReLU + JK --------
__global__ void __launch_bounds__(256)
k_agg(const float* __restrict__ bconv, const float* __restrict__ blin,
      const float* __restrict__ lng, const float* __restrict__ lnb,
      int layer, int n) {
    int gwarp = (blockIdx.x * blockDim.x + threadIdx.x) >> 5;
    if (gwarp >= n) return;
    int lane = threadIdx.x & 31;
    int node = gwarp;

    float dn = g_dinv[node];
    const float4* HC = (const float4*)g_hc;
    const float4* HL = (const float4*)g_hl;

    float4 acc = make_float4(0.f, 0.f, 0.f, 0.f);
    int b = g_off[node], e = g_off[node + 1];
    int i = b;
    for (; i + 2 <= e; i += 2) {
        int s0 = g_srcs[i], s1 = g_srcs[i + 1];
        float w0 = g_wsc[i] * dn, w1 = g_wsc[i + 1] * dn;
        float4 h0 = HC[s0 * 32 + lane];
        float4 h1 = HC[s1 * 32 + lane];
        acc.x += h0.x * w0 + h1.x * w1;
        acc.y += h0.y * w0 + h1.y * w1;
        acc.z += h0.z * w0 + h1.z * w1;
        acc.w += h0.w * w0 + h1.w * w1;
    }
    if (i < e) {
        int s0 = g_srcs[i];
        float w0 = g_wsc[i] * dn;
        float4 h0 = HC[s0 * 32 + lane];
        acc.x += h0.x * w0; acc.y += h0.y * w0;
        acc.z += h0.z * w0; acc.w += h0.w * w0;
    }
    float sd = dn * dn;
    float4 hs = HC[node * 32 + lane];
    acc.x += hs.x * sd; acc.y += hs.y * sd; acc.z += hs.z * sd; acc.w += hs.w * sd;

    float4 hl4 = HL[node * 32 + lane];
    float4 bc  = ((const float4*)bconv)[lane];
    float4 bl  = ((const float4*)blin)[lane];
    float v0 = acc.x + bc.x + hl4.x + bl.x;
    float v1 = acc.y + bc.y + hl4.y + bl.y;
    float v2 = acc.z + bc.z + hl4.z + bl.z;
    float v3 = acc.w + bc.w + hl4.w + bl.w;

    float mu = wredsum(v0 + v1 + v2 + v3) * (1.0f / 128.0f);
    float d0 = v0 - mu, d1 = v1 - mu, d2 = v2 - mu, d3 = v3 - mu;
    float var = wredsum(d0 * d0 + d1 * d1 + d2 * d2 + d3 * d3) * (1.0f / 128.0f);
    float inv = rsqrtf(var + EPS);

    float4 g4 = ((const float4*)lng)[lane];
    float4 b4 = ((const float4*)lnb)[lane];
    v0 = fmaxf(0.f, d0 * inv * g4.x + b4.x);
    v1 = fmaxf(0.f, d1 * inv * g4.y + b4.y);
    v2 = fmaxf(0.f, d2 * inv * g4.z + b4.z);
    v3 = fmaxf(0.f, d3 * inv * g4.w + b4.w);

    float4 out = make_float4(v0, v1, v2, v3);
    ((float4*)g_x)[node * 32 + lane] = out;
    float4* XF = (float4*)g_xf;
    if (layer == 0) {
        XF[node * 32 + lane] = out;
    } else {
        float4 r = XF[node * 32 + lane];
        r.x += v0; r.y += v1; r.z += v2; r.w += v3;
        XF[node * 32 + lane] = r;
    }
}

// ---------------- prediction GEMM: out[N,40] = xf @ Wpred + bpred -----------
__global__ void __launch_bounds__(256)
k_pred(const float* __restrict__ Wp, const float* __restrict__ bp,
       float* __restrict__ out, int n) {
    __shared__ float xs[50 * 128];
    __shared__ float ws[128 * 40];
    int tid = threadIdx.x;
    int row0 = blockIdx.x * 50;

    for (int t = tid; t < 50 * 128; t += 256) {
        int r = t >> 7, c = t & 127;
        int gr = row0 + r;
        xs[t] = (gr < n) ? g_xf[gr * 128 + c] : 0.f;
    }
    for (int t = tid; t < 128 * 40; t += 256) ws[t] = Wp[t];
    __syncthreads();

    if (tid < 250) {
        int cg = tid % 10;
        int rg = tid / 10;
        int r0 = 2 * rg, r1 = r0 + 1;
        unsigned long long a00 = 0ULL, a01 = 0ULL, a10 = 0ULL, a11 = 0ULL;
        #pragma unroll 4
        for (int k = 0; k < 128; k++) {
            float x0 = xs[r0 * 128 + k];
            float x1 = xs[r1 * 128 + k];
            float4 w4 = *(const float4*)&ws[k * 40 + cg * 4];
            unsigned long long wp0 = pk2(w4.x, w4.y);
            unsigned long long wp1 = pk2(w4.z, w4.w);
            unsigned long long ad0 = pk2(x0, x0);
            unsigned long long ad1 = pk2(x1, x1);
            f2fma(a00, ad0, wp0); f2fma(a01, ad0, wp1);
            f2fma(a10, ad1, wp0); f2fma(a11, ad1, wp1);
        }
        int c0 = cg * 4;
        float b0 = bp[c0], b1 = bp[c0 + 1], b2 = bp[c0 + 2], b3 = bp[c0 + 3];
        float lo, hi;
        int gr0 = row0 + r0, gr1 = row0 + r1;
        if (gr0 < n) {
            up2(lo, hi, a00);
            out[gr0 * 40 + c0]     = lo + b0;
            out[gr0 * 40 + c0 + 1] = hi + b1;
            up2(lo, hi, a01);
            out[gr0 * 40 + c0 + 2] = lo + b2;
            out[gr0 * 40 + c0 + 3] = hi + b3;
        }
        if (gr1 < n) {
            up2(lo, hi, a10);
            out[gr1 * 40 + c0]     = lo + b0;
            out[gr1 * 40 + c0 + 1] = hi + b1;
            up2(lo, hi, a11);
            out[gr1 * 40 + c0 + 2] = lo + b2;
            out[gr1 * 40 + c0 + 3] = hi + b3;
        }
    }
}

// ---------------- launch ----------------
extern "C" void kernel_launch(void* const* d_in, const int* in_sizes, int n_in,
                              void* d_out, int out_size) {
    const float* x      = (const float*)d_in[0];
    const int*   ei     = (const int*)  d_in[1];
    const float* Wconv  = (const float*)d_in[2];
    const float* bconv  = (const float*)d_in[3];
    const float* Wlin   = (const float*)d_in[4];
    const float* blin   = (const float*)d_in[5];
    const float* ln_g   = (const float*)d_in[6];
    const float* ln_b   = (const float*)d_in[7];
    const float* Wpred  = (const float*)d_in[8];
    const float* bpred  = (const float*)d_in[9];
    float* out = (float*)d_out;

    int n = in_sizes[0] / DD;     // 50000
    int e = in_sizes[1] / 2;      // 600000

    static bool attr_set = false;
    if (!attr_set) {
        cudaFuncSetAttribute(k_mma, cudaFuncAttributeMaxDynamicSharedMemorySize,
                             MMA_SMEM);
        attr_set = true;
    }

    int nb = (n + 1023) / 1024;

    k_zero<<<(n + 255) / 256, 256>>>(n);
    k_deg <<<(e + 255) / 256, 256>>>(ei, e);
    k_dinv<<<(n + 255) / 256, 256>>>(n);
    k_scan1<<<nb, 1024>>>(n);
    k_scan2<<<1, 32>>>(nb, n);
    k_scan3<<<nb, 1024>>>(n);
    k_place<<<(e + 255) / 256, 256>>>(ei, e);
    k_wprep<<<(LL * 128 * 128 + 255) / 256, 256>>>(Wconv, Wlin);

    float* g_x_dev = nullptr;
    cudaGetSymbolAddress((void**)&g_x_dev, g_x);

    dim3 gmma((n + 127) / 128, 2);
    for (int i = 0; i < LL; i++) {
        const float* Xin = (i == 0) ? x : (const float*)g_x_dev;
        k_mma<<<gmma, 256, MMA_SMEM>>>(Xin, i, n);
        k_agg<<<(n + 7) / 8, 256>>>(bconv + i * HH, blin + i * HH,
                                    ln_g + i * HH, ln_b + i * HH, i, n);
    }

    k_pred<<<(n + 49) / 50, 256>>>(Wpred, bpred, out, n);
}

// round 6
// speedup vs baseline: 1.4501x; 1.1012x over previous
#include <cuda_runtime.h>
#include <cuda_bf16.h>
#include <stdint.h>

// Problem constants (fixed by the dataset)
#define NN 50000
#define EE 600000
#define DD 128
#define HH 128
#define CC 40
#define LL 3
#define EPS 1e-5f

#define NPAD (((NN + 127) / 128) * 128)   // 50048 padded rows
#define SA 136                            // padded smem row stride (bf16 elems)
#define WIMG 17408                        // 128 * 136 bf16 per W image

// ---------------- scratch (static __device__, no allocation) ----------------
__device__ float g_hc[NN * HH];           // x @ Wconv[i]
__device__ float g_hl[NN * HH];           // x @ Wlin[i]
__device__ float g_xf[NN * HH];           // JK sum
__device__ __nv_bfloat16 g_xh[NPAD * HH]; // activations hi plane
__device__ __nv_bfloat16 g_xl[NPAD * HH]; // activations lo plane
__device__ float g_dinv[NN];
__device__ int   g_cnt[NN];
__device__ int   g_cur[NN];
__device__ int   g_off[NN + 1];
__device__ int   g_part[128];
__device__ int   g_srcs[EE];
__device__ float g_wsc[EE];
// Preformatted W: [layer][conv-hi, conv-lo, lin-hi, lin-lo][128n x 136k] bf16
__device__ __nv_bfloat16 g_wb[LL * 4 * WIMG];

// ---------------- small PTX helpers ----------------
__device__ __forceinline__ uint32_t smem_u32(const void* p) {
    uint32_t a;
    asm("{ .reg .u64 t; cvta.to.shared.u64 t, %1; cvt.u32.u64 %0, t; }"
        : "=r"(a) : "l"(p));
    return a;
}
__device__ __forceinline__ void ldsm_x4(uint32_t* r, uint32_t addr) {
    asm volatile("ldmatrix.sync.aligned.m8n8.x4.shared.b16 {%0,%1,%2,%3}, [%4];"
        : "=r"(r[0]), "=r"(r[1]), "=r"(r[2]), "=r"(r[3]) : "r"(addr));
}
__device__ __forceinline__ void ldsm_x2(uint32_t* r, uint32_t addr) {
    asm volatile("ldmatrix.sync.aligned.m8n8.x2.shared.b16 {%0,%1}, [%2];"
        : "=r"(r[0]), "=r"(r[1]) : "r"(addr));
}
__device__ __forceinline__ void mma_bf16(float* c, const uint32_t* a,
                                         const uint32_t* b) {
    asm volatile("mma.sync.aligned.m16n8k16.row.col.f32.bf16.bf16.f32 "
                 "{%0,%1,%2,%3}, {%4,%5,%6,%7}, {%8,%9}, {%0,%1,%2,%3};"
                 : "+f"(c[0]), "+f"(c[1]), "+f"(c[2]), "+f"(c[3])
                 : "r"(a[0]), "r"(a[1]), "r"(a[2]), "r"(a[3]),
                   "r"(b[0]), "r"(b[1]));
}

// ---------------- f32x2 helpers (pred kernel) ----------------
__device__ __forceinline__ unsigned long long pk2(float lo, float hi) {
    unsigned long long r;
    asm("mov.b64 %0, {%1, %2};" : "=l"(r) : "f"(lo), "f"(hi));
    return r;
}
__device__ __forceinline__ void up2(float &lo, float &hi, unsigned long long v) {
    asm("mov.b64 {%0, %1}, %2;" : "=f"(lo), "=f"(hi) : "l"(v));
}
__device__ __forceinline__ void f2fma(unsigned long long &d,
                                      unsigned long long a,
                                      unsigned long long b) {
    asm("fma.rn.f32x2 %0, %1, %2, %0;" : "+l"(d) : "l"(a), "l"(b));
}
__device__ __forceinline__ float wredsum(float v) {
    #pragma unroll
    for (int o = 16; o > 0; o >>= 1) v += __shfl_xor_sync(0xffffffffu, v, o);
    return v;
}

// hi/lo bf16 split pack: low half = first value
__device__ __forceinline__ void split2(float a, float b, uint32_t &hp, uint32_t &lp) {
    __nv_bfloat16 ha = __float2bfloat16(a);
    __nv_bfloat16 hb = __float2bfloat16(b);
    __nv_bfloat16 la = __float2bfloat16(a - __bfloat162float(ha));
    __nv_bfloat16 lb = __float2bfloat16(b - __bfloat162float(hb));
    hp = (uint32_t)__bfloat16_as_ushort(ha) | ((uint32_t)__bfloat16_as_ushort(hb) << 16);
    lp = (uint32_t)__bfloat16_as_ushort(la) | ((uint32_t)__bfloat16_as_ushort(lb) << 16);
}

// ---------------- preprocessing ----------------
__global__ void k_zero(int n) {
    int i = blockIdx.x * blockDim.x + threadIdx.x;
    if (i < n) { g_cnt[i] = 0; g_cur[i] = 0; }
}
__global__ void k_deg(const int* __restrict__ ei, int e) {
    int i = blockIdx.x * blockDim.x + threadIdx.x;
    if (i < e) atomicAdd(&g_cnt[ei[e + i]], 1);
}
// warp-shuffle block scan (1024 threads); also computes dinv
__global__ void k_scan1(int n) {
    __shared__ int ws[32];
    int t = threadIdx.x, idx = blockIdx.x * 1024 + t;
    int val = (idx < n) ? g_cnt[idx] : 0;
    if (idx < n) g_dinv[idx] = rsqrtf((float)val + 1.0f);
    int lane = t & 31, w = t >> 5;
    int inc = val;
    #pragma unroll
    for (int o = 1; o < 32; o <<= 1) {
        int u = __shfl_up_sync(0xffffffffu, inc, o);
        if (lane >= o) inc += u;
    }
    if (lane == 31) ws[w] = inc;
    __syncthreads();
    if (w == 0) {
        int s = ws[lane];
        int sc = s;
        #pragma unroll
        for (int o = 1; o < 32; o <<= 1) {
            int u = __shfl_up_sync(0xffffffffu, sc, o);
            if (lane >= o) sc += u;
        }
        ws[lane] = sc - s;                       // exclusive warp prefix
        if (lane == 31) g_part[blockIdx.x] = sc; // block total
    }
    __syncthreads();
    if (idx < n) g_off[idx] = inc - val + ws[w];
}
__global__ void k_scan2(int nb, int n) {
    if (threadIdx.x == 0 && blockIdx.x == 0) {
        int run = 0;
        for (int b = 0; b < nb; b++) { int tmp = g_part[b]; g_part[b] = run; run += tmp; }
        g_off[n] = run;
    }
}
__global__ void k_scan3(int n) {
    int idx = blockIdx.x * 1024 + threadIdx.x;
    if (idx < n) g_off[idx] += g_part[blockIdx.x];
}
__global__ void k_place(const int* __restrict__ ei, int e) {
    int i = blockIdx.x * blockDim.x + threadIdx.x;
    if (i < e) {
        int s = ei[i];
        int d = ei[e + i];
        int p = g_off[d] + atomicAdd(&g_cur[d], 1);
        g_srcs[p] = s;
        g_wsc[p]  = g_dinv[s];
    }
}

// ---------------- W preformat: fp32 -> bf16 hi/lo padded [n][k] images ------
__global__ void k_wprep(const float* __restrict__ Wconv,
                        const float* __restrict__ Wlin) {
    int i = blockIdx.x * blockDim.x + threadIdx.x;
    if (i >= LL * 128 * 128) return;
    int l = i >> 14;
    int k = (i >> 7) & 127;
    int n = i & 127;
    float c = Wconv[l * 16384 + k * 128 + n];
    float v = Wlin [l * 16384 + k * 128 + n];
    int pos = n * SA + k;
    __nv_bfloat16 ch = __float2bfloat16(c);
    __nv_bfloat16 cl = __float2bfloat16(c - __bfloat162float(ch));
    __nv_bfloat16 vh = __float2bfloat16(v);
    __nv_bfloat16 vl = __float2bfloat16(v - __bfloat162float(vh));
    __nv_bfloat16* base = g_wb + (size_t)l * 4 * WIMG;
    base[0 * WIMG + pos] = ch;   // conv hi
    base[1 * WIMG + pos] = cl;   // conv lo
    base[2 * WIMG + pos] = vh;   // lin hi
    base[3 * WIMG + pos] = vl;   // lin lo
}

// ---------------- layer-0 input: fp32 -> bf16 hi/lo planes (zero-padded) ----
__global__ void k_xprep(const float* __restrict__ x, int n) {
    int i = blockIdx.x * blockDim.x + threadIdx.x;   // one float4 group each
    if (i >= NPAD * 32) return;
    int row = i >> 5;
    float4 v = make_float4(0.f, 0.f, 0.f, 0.f);
    if (row < n) v = ((const float4*)x)[i];
    uint32_t h0, l0, h1, l1;
    split2(v.x, v.y, h0, l0);
    split2(v.z, v.w, h1, l1);
    ((uint2*)g_xh)[i] = make_uint2(h0, h1);
    ((uint2*)g_xl)[i] = make_uint2(l0, l1);
}

// ---------------- tensor-core GEMM: [hc | hl] = X @ [Wconv | Wlin] ----------
// CTA: 128 rows x 256 cols, 512 threads (16 warps, 4m x 4n warp grid).
// smem: A hi/lo [128][136] bf16 each, then 4 B images (conv hi/lo, lin hi/lo).
#define OFF_AL 34816
#define OFF_B  69632
#define MMA_SMEM (OFF_B + 4 * 34816)   // 208896 bytes

__global__ void __launch_bounds__(512, 1)
k_mma(int layer, int nrows) {
    extern __shared__ char smc[];
    uint32_t sb = smem_u32(smc);
    int tid = threadIdx.x;
    int lane = tid & 31;
    int wid = tid >> 5;
    int row0 = blockIdx.x * 128;

    // ---- B copy: 4 images, contiguous 139264 B ----
    {
        const uint4* src = (const uint4*)(g_wb + (size_t)layer * 4 * WIMG);
        uint4* dst = (uint4*)(smc + OFF_B);
        #pragma unroll
        for (int t = tid; t < 8704; t += 512) dst[t] = src[t];
    }
    // ---- A copy: preformatted hi/lo planes (padded rows -> no bounds) ----
    {
        const uint4* sh = (const uint4*)g_xh + (size_t)row0 * 16;
        const uint4* sl = (const uint4*)g_xl + (size_t)row0 * 16;
        #pragma unroll
        for (int t = tid; t < 4096; t += 512) {
            int plane = t >> 11, r = (t >> 4) & 127, c = t & 15;
            const uint4* src = plane ? sl : sh;
            *(uint4*)(smc + plane * OFF_AL + r * (SA * 2) + c * 16) = src[r * 16 + c];
        }
    }
    __syncthreads();

    // ---- MMA mainloop ----
    int wr  = wid >> 2;           // warp row 0-3 (32 rows each)
    int wc2 = wid & 3;            // warp col 0-3 (64 cols each over 256)
    int sel = wc2 >> 1;           // 0 = conv, 1 = lin
    int nb64 = wc2 & 1;           // 64-col half within sel

    int arow = wr * 32 + (lane & 7) + ((lane & 8) ? 8 : 0);
    int akof = (lane & 16) ? 8 : 0;
    uint32_t aH = sb + (uint32_t)(arow * SA + akof) * 2;
    uint32_t aL = aH + OFF_AL;

    int brow = nb64 * 64 + (lane & 7);
    int bkof = (lane & 8) ? 8 : 0;
    uint32_t bH = sb + OFF_B + (uint32_t)sel * 69632 + (uint32_t)(brow * SA + bkof) * 2;
    uint32_t bL = bH + 34816;

    float c[2][8][4];
    #pragma unroll
    for (int i = 0; i < 2; i++)
        #pragma unroll
        for (int j = 0; j < 8; j++)
            #pragma unroll
            for (int q = 0; q < 4; q++) c[i][j][q] = 0.f;

    #pragma unroll
    for (int ks = 0; ks < 8; ks++) {
        uint32_t ka = ks * 32;    // 16 bf16 * 2 B
        uint32_t ah0[4], ah1[4], al0[4], al1[4];
        ldsm_x4(ah0, aH + ka);
        ldsm_x4(ah1, aH + ka + 16 * SA * 2);
        ldsm_x4(al0, aL + ka);
        ldsm_x4(al1, aL + ka + 16 * SA * 2);
        #pragma unroll
        for (int nt = 0; nt < 8; nt++) {
            uint32_t bh[2], bl[2];
            ldsm_x2(bh, bH + nt * (8 * SA * 2) + ka);
            ldsm_x2(bl, bL + nt * (8 * SA * 2) + ka);
            mma_bf16(c[0][nt], ah0, bh);
            mma_bf16(c[1][nt], ah1, bh);
            mma_bf16(c[0][nt], ah0, bl);
            mma_bf16(c[1][nt], ah1, bl);
            mma_bf16(c[0][nt], al0, bh);
            mma_bf16(c[1][nt], al1, bh);
        }
    }

    // ---- epilogue ----
    float* outp = sel ? g_hl : g_hc;
    int g  = lane >> 2;
    int tg = lane & 3;
    #pragma unroll
    for (int mt = 0; mt < 2; mt++) {
        int r0 = row0 + wr * 32 + mt * 16 + g;
        #pragma unroll
        for (int nt = 0; nt < 8; nt++) {
            int col = nb64 * 64 + nt * 8 + tg * 2;
            if (r0 < nrows)
                *(float2*)(outp + (size_t)r0 * 128 + col) =
                    make_float2(c[mt][nt][0], c[mt][nt][1]);
            if (r0 + 8 < nrows)
                *(float2*)(outp + (size_t)(r0 + 8) * 128 + col) =
                    make_float2(c[mt][nt][2], c[mt][nt][3]);
        }
    }
}

// ---------------- fused aggregate + bias + residual + LN + ReLU + JK --------
// Writes next-layer activations as bf16 hi/lo planes.
__global__ void __launch_bounds__(256)
k_agg(const float* __restrict__ bconv, const float* __restrict__ blin,
      const float* __restrict__ lng, const float* __restrict__ lnb,
      int layer, int n) {
    int gwarp = (blockIdx.x * blockDim.x + threadIdx.x) >> 5;
    if (gwarp >= n) return;
    int lane = threadIdx.x & 31;
    int node = gwarp;

    float dn = g_dinv[node];
    const float4* HC = (const float4*)g_hc;
    const float4* HL = (const float4*)g_hl;

    float4 acc = make_float4(0.f, 0.f, 0.f, 0.f);
    int b = g_off[node], e = g_off[node + 1];
    int i = b;
    for (; i + 2 <= e; i += 2) {
        int s0 = g_srcs[i], s1 = g_srcs[i + 1];
        float w0 = g_wsc[i] * dn, w1 = g_wsc[i + 1] * dn;
        float4 h0 = HC[s0 * 32 + lane];
        float4 h1 = HC[s1 * 32 + lane];
        acc.x += h0.x * w0 + h1.x * w1;
        acc.y += h0.y * w0 + h1.y * w1;
        acc.z += h0.z * w0 + h1.z * w1;
        acc.w += h0.w * w0 + h1.w * w1;
    }
    if (i < e) {
        int s0 = g_srcs[i];
        float w0 = g_wsc[i] * dn;
        float4 h0 = HC[s0 * 32 + lane];
        acc.x += h0.x * w0; acc.y += h0.y * w0;
        acc.z += h0.z * w0; acc.w += h0.w * w0;
    }
    float sd = dn * dn;
    float4 hs = HC[node * 32 + lane];
    acc.x += hs.x * sd; acc.y += hs.y * sd; acc.z += hs.z * sd; acc.w += hs.w * sd;

    float4 hl4 = HL[node * 32 + lane];
    float4 bc  = ((const float4*)bconv)[lane];
    float4 bl  = ((const float4*)blin)[lane];
    float v0 = acc.x + bc.x + hl4.x + bl.x;
    float v1 = acc.y + bc.y + hl4.y + bl.y;
    float v2 = acc.z + bc.z + hl4.z + bl.z;
    float v3 = acc.w + bc.w + hl4.w + bl.w;

    float mu = wredsum(v0 + v1 + v2 + v3) * (1.0f / 128.0f);
    float d0 = v0 - mu, d1 = v1 - mu, d2 = v2 - mu, d3 = v3 - mu;
    float var = wredsum(d0 * d0 + d1 * d1 + d2 * d2 + d3 * d3) * (1.0f / 128.0f);
    float inv = rsqrtf(var + EPS);

    float4 g4 = ((const float4*)lng)[lane];
    float4 b4 = ((const float4*)lnb)[lane];
    v0 = fmaxf(0.f, d0 * inv * g4.x + b4.x);
    v1 = fmaxf(0.f, d1 * inv * g4.y + b4.y);
    v2 = fmaxf(0.f, d2 * inv * g4.z + b4.z);
    v3 = fmaxf(0.f, d3 * inv * g4.w + b4.w);

    // next-layer activations as hi/lo planes
    uint32_t h0, l0, h1, l1;
    split2(v0, v1, h0, l0);
    split2(v2, v3, h1, l1);
    ((uint2*)g_xh)[node * 32 + lane] = make_uint2(h0, h1);
    ((uint2*)g_xl)[node * 32 + lane] = make_uint2(l0, l1);

    float4* XF = (float4*)g_xf;
    if (layer == 0) {
        XF[node * 32 + lane] = make_float4(v0, v1, v2, v3);
    } else {
        float4 r = XF[node * 32 + lane];
        r.x += v0; r.y += v1; r.z += v2; r.w += v3;
        XF[node * 32 + lane] = r;
    }
}

// ---------------- prediction GEMM: out[N,40] = xf @ Wpred + bpred -----------
__global__ void __launch_bounds__(256)
k_pred(const float* __restrict__ Wp, const float* __restrict__ bp,
       float* __restrict__ out, int n) {
    __shared__ float xs[50 * 128];
    __shared__ float ws[128 * 40];
    int tid = threadIdx.x;
    int row0 = blockIdx.x * 50;

    for (int t = tid; t < 50 * 128; t += 256) {
        int r = t >> 7, c = t & 127;
        int gr = row0 + r;
        xs[t] = (gr < n) ? g_xf[gr * 128 + c] : 0.f;
    }
    for (int t = tid; t < 128 * 40; t += 256) ws[t] = Wp[t];
    __syncthreads();

    if (tid < 250) {
        int cg = tid % 10;
        int rg = tid / 10;
        int r0 = 2 * rg, r1 = r0 + 1;
        unsigned long long a00 = 0ULL, a01 = 0ULL, a10 = 0ULL, a11 = 0ULL;
        #pragma unroll 4
        for (int k = 0; k < 128; k++) {
            float x0 = xs[r0 * 128 + k];
            float x1 = xs[r1 * 128 + k];
            float4 w4 = *(const float4*)&ws[k * 40 + cg * 4];
            unsigned long long wp0 = pk2(w4.x, w4.y);
            unsigned long long wp1 = pk2(w4.z, w4.w);
            unsigned long long ad0 = pk2(x0, x0);
            unsigned long long ad1 = pk2(x1, x1);
            f2fma(a00, ad0, wp0); f2fma(a01, ad0, wp1);
            f2fma(a10, ad1, wp0); f2fma(a11, ad1, wp1);
        }
        int c0 = cg * 4;
        float b0 = bp[c0], b1 = bp[c0 + 1], b2 = bp[c0 + 2], b3 = bp[c0 + 3];
        float lo, hi;
        int gr0 = row0 + r0, gr1 = row0 + r1;
        if (gr0 < n) {
            up2(lo, hi, a00);
            out[gr0 * 40 + c0]     = lo + b0;
            out[gr0 * 40 + c0 + 1] = hi + b1;
            up2(lo, hi, a01);
            out[gr0 * 40 + c0 + 2] = lo + b2;
            out[gr0 * 40 + c0 + 3] = hi + b3;
        }
        if (gr1 < n) {
            up2(lo, hi, a10);
            out[gr1 * 40 + c0]     = lo + b0;
            out[gr1 * 40 + c0 + 1] = hi + b1;
            up2(lo, hi, a11);
            out[gr1 * 40 + c0 + 2] = lo + b2;
            out[gr1 * 40 + c0 + 3] = hi + b3;
        }
    }
}

// ---------------- launch ----------------
extern "C" void kernel_launch(void* const* d_in, const int* in_sizes, int n_in,
                              void* d_out, int out_size) {
    const float* x      = (const float*)d_in[0];
    const int*   ei     = (const int*)  d_in[1];
    const float* Wconv  = (const float*)d_in[2];
    const float* bconv  = (const float*)d_in[3];
    const float* Wlin   = (const float*)d_in[4];
    const float* blin   = (const float*)d_in[5];
    const float* ln_g   = (const float*)d_in[6];
    const float* ln_b   = (const float*)d_in[7];
    const float* Wpred  = (const float*)d_in[8];
    const float* bpred  = (const float*)d_in[9];
    float* out = (float*)d_out;

    int n = in_sizes[0] / DD;     // 50000
    int e = in_sizes[1] / 2;      // 600000

    static bool attr_set = false;
    if (!attr_set) {
        cudaFuncSetAttribute(k_mma, cudaFuncAttributeMaxDynamicSharedMemorySize,
                             MMA_SMEM);
        attr_set = true;
    }

    int nb = (n + 1023) / 1024;

    k_zero<<<(n + 255) / 256, 256>>>(n);
    k_deg <<<(e + 255) / 256, 256>>>(ei, e);
    k_scan1<<<nb, 1024>>>(n);
    k_scan2<<<1, 32>>>(nb, n);
    k_scan3<<<nb, 1024>>>(n);
    k_place<<<(e + 255) / 256, 256>>>(ei, e);
    k_wprep<<<(LL * 128 * 128 + 255) / 256, 256>>>(Wconv, Wlin);
    k_xprep<<<(NPAD * 32 + 255) / 256, 256>>>(x, n);

    int ntiles = (n + 127) / 128;
    for (int i = 0; i < LL; i++) {
        k_mma<<<ntiles, 512, MMA_SMEM>>>(i, n);
        k_agg<<<(n + 7) / 8, 256>>>(bconv + i * HH, blin + i * HH,
                                    ln_g + i * HH, ln_b + i * HH, i, n);
    }

    k_pred<<<(n + 49) / 50, 256>>>(Wpred, bpred, out, n);
}

// round 7
// speedup vs baseline: 1.6461x; 1.1351x over previous
#include <cuda_runtime.h>
#include <cuda_bf16.h>
#include <stdint.h>

// Problem constants (fixed by the dataset)
#define NN 50000
#define EE 600000
#define DD 128
#define HH 128
#define CC 40
#define LL 3
#define EPS 1e-5f

#define NPAD (((NN + 127) / 128) * 128)   // 50048 padded rows
#define SA 136                            // padded smem row stride (bf16 elems)
#define WIMG 17408                        // 128 * 136 bf16 per W image
#define WIMGP 8704                        // 64 * 136 bf16 per Wpred image

// ---------------- scratch (static __device__, no allocation) ----------------
__device__ float g_hc[NN * HH];           // x @ Wconv[i]
__device__ float g_hl[NN * HH];           // x @ Wlin[i]
__device__ float g_xf[NN * HH];           // JK sum (layers 0,1)
__device__ __nv_bfloat16 g_xh[NPAD * HH]; // activations / xf hi plane
__device__ __nv_bfloat16 g_xl[NPAD * HH]; // activations / xf lo plane
__device__ float g_dinv[NN];
__device__ int   g_cnt[NN];               // degree; restored to 0 by k_place
__device__ int   g_off[NN + 1];
__device__ int   g_part[128];
__device__ int   g_srcs[EE];
__device__ float g_wsc[EE];
// Preformatted W: [layer][conv-hi, conv-lo, lin-hi, lin-lo][128n x 136k] bf16
__device__ __nv_bfloat16 g_wb[LL * 4 * WIMG];
// Preformatted Wpred: [hi, lo][64n x 136k] bf16 (rows 40-63 zero)
__device__ __nv_bfloat16 g_wbp[2 * WIMGP];

// ---------------- small PTX helpers ----------------
__device__ __forceinline__ uint32_t smem_u32(const void* p) {
    uint32_t a;
    asm("{ .reg .u64 t; cvta.to.shared.u64 t, %1; cvt.u32.u64 %0, t; }"
        : "=r"(a) : "l"(p));
    return a;
}
__device__ __forceinline__ void ldsm_x4(uint32_t* r, uint32_t addr) {
    asm volatile("ldmatrix.sync.aligned.m8n8.x4.shared.b16 {%0,%1,%2,%3}, [%4];"
        : "=r"(r[0]), "=r"(r[1]), "=r"(r[2]), "=r"(r[3]) : "r"(addr));
}
__device__ __forceinline__ void ldsm_x2(uint32_t* r, uint32_t addr) {
    asm volatile("ldmatrix.sync.aligned.m8n8.x2.shared.b16 {%0,%1}, [%2];"
        : "=r"(r[0]), "=r"(r[1]) : "r"(addr));
}
__device__ __forceinline__ void mma_bf16(float* c, const uint32_t* a,
                                         const uint32_t* b) {
    asm volatile("mma.sync.aligned.m16n8k16.row.col.f32.bf16.bf16.f32 "
                 "{%0,%1,%2,%3}, {%4,%5,%6,%7}, {%8,%9}, {%0,%1,%2,%3};"
                 : "+f"(c[0]), "+f"(c[1]), "+f"(c[2]), "+f"(c[3])
                 : "r"(a[0]), "r"(a[1]), "r"(a[2]), "r"(a[3]),
                   "r"(b[0]), "r"(b[1]));
}
__device__ __forceinline__ float wredsum(float v) {
    #pragma unroll
    for (int o = 16; o > 0; o >>= 1) v += __shfl_xor_sync(0xffffffffu, v, o);
    return v;
}
__device__ __forceinline__ int wredsumi(int v) {
    #pragma unroll
    for (int o = 16; o > 0; o >>= 1) v += __shfl_xor_sync(0xffffffffu, v, o);
    return v;
}
// hi/lo bf16 split pack: low half = first value
__device__ __forceinline__ void split2(float a, float b, uint32_t &hp, uint32_t &lp) {
    __nv_bfloat16 ha = __float2bfloat16(a);
    __nv_bfloat16 hb = __float2bfloat16(b);
    __nv_bfloat16 la = __float2bfloat16(a - __bfloat162float(ha));
    __nv_bfloat16 lb = __float2bfloat16(b - __bfloat162float(hb));
    hp = (uint32_t)__bfloat16_as_ushort(ha) | ((uint32_t)__bfloat16_as_ushort(hb) << 16);
    lp = (uint32_t)__bfloat16_as_ushort(la) | ((uint32_t)__bfloat16_as_ushort(lb) << 16);
}

// ---------------- preprocessing ----------------
__global__ void k_deg(const int* __restrict__ ei, int e) {
    int i = blockIdx.x * blockDim.x + threadIdx.x;
    if (i < e) atomicAdd(&g_cnt[ei[e + i]], 1);
}
// warp-shuffle block scan (1024 threads); also computes dinv
__global__ void k_scan1(int n) {
    __shared__ int ws[32];
    int t = threadIdx.x, idx = blockIdx.x * 1024 + t;
    int val = (idx < n) ? g_cnt[idx] : 0;
    if (idx < n) g_dinv[idx] = rsqrtf((float)val + 1.0f);
    int lane = t & 31, w = t >> 5;
    int inc = val;
    #pragma unroll
    for (int o = 1; o < 32; o <<= 1) {
        int u = __shfl_up_sync(0xffffffffu, inc, o);
        if (lane >= o) inc += u;
    }
    if (lane == 31) ws[w] = inc;
    __syncthreads();
    if (w == 0) {
        int s = ws[lane];
        int sc = s;
        #pragma unroll
        for (int o = 1; o < 32; o <<= 1) {
            int u = __shfl_up_sync(0xffffffffu, sc, o);
            if (lane >= o) sc += u;
        }
        ws[lane] = sc - s;                       // exclusive warp prefix
        if (lane == 31) g_part[blockIdx.x] = sc; // block total
    }
    __syncthreads();
    if (idx < n) g_off[idx] = inc - val + ws[w];
}
// adds cross-block base (warp-reduced from g_part) and writes g_off[n]=e
__global__ void k_scan3(int n, int e) {
    __shared__ int base;
    int t = threadIdx.x;
    if (t < 32) {
        int s = 0;
        for (int j = t; j < blockIdx.x; j += 32) s += g_part[j];
        s = wredsumi(s);
        if (t == 0) base = s;
    }
    __syncthreads();
    int idx = blockIdx.x * 1024 + t;
    if (idx < n) g_off[idx] += base;
    if (blockIdx.x == 0 && t == 0) g_off[n] = e;
}
// slot via atomicSub on g_cnt -> g_cnt returns to all-zero afterwards
__global__ void k_place(const int* __restrict__ ei, int e) {
    int i = blockIdx.x * blockDim.x + threadIdx.x;
    if (i < e) {
        int s = ei[i];
        int d = ei[e + i];
        int p = g_off[d] + atomicSub(&g_cnt[d], 1) - 1;
        g_srcs[p] = s;
        g_wsc[p]  = g_dinv[s];
    }
}

// ---------------- W preformat: fp32 -> bf16 hi/lo padded [n][k] images ------
__global__ void k_wprep(const float* __restrict__ Wconv,
                        const float* __restrict__ Wlin,
                        const float* __restrict__ Wpred) {
    int i = blockIdx.x * blockDim.x + threadIdx.x;
    if (i < LL * 128 * 128) {
        int l = i >> 14;
        int k = (i >> 7) & 127;
        int n = i & 127;
        float c = Wconv[l * 16384 + k * 128 + n];
        float v = Wlin [l * 16384 + k * 128 + n];
        int pos = n * SA + k;
        uint32_t dummyh, dummyl;
        (void)dummyh; (void)dummyl;
        __nv_bfloat16 ch = __float2bfloat16(c);
        __nv_bfloat16 cl = __float2bfloat16(c - __bfloat162float(ch));
        __nv_bfloat16 vh = __float2bfloat16(v);
        __nv_bfloat16 vl = __float2bfloat16(v - __bfloat162float(vh));
        __nv_bfloat16* base = g_wb + (size_t)l * 4 * WIMG;
        base[0 * WIMG + pos] = ch;   // conv hi
        base[1 * WIMG + pos] = cl;   // conv lo
        base[2 * WIMG + pos] = vh;   // lin hi
        base[3 * WIMG + pos] = vl;   // lin lo
    } else if (i < LL * 128 * 128 + 64 * 128) {
        int j = i - LL * 128 * 128;
        int n = j >> 7;              // 0..63 output col
        int k = j & 127;
        float v = (n < CC) ? Wpred[k * CC + n] : 0.f;
        __nv_bfloat16 vh = __float2bfloat16(v);
        __nv_bfloat16 vl = __float2bfloat16(v - __bfloat162float(vh));
        int pos = n * SA + k;
        g_wbp[pos]         = vh;
        g_wbp[WIMGP + pos] = vl;
    }
}

// ---------------- layer-0 input: fp32 -> bf16 hi/lo planes (zero-padded) ----
__global__ void k_xprep(const float* __restrict__ x, int n) {
    int i = blockIdx.x * blockDim.x + threadIdx.x;   // one float4 group each
    if (i >= NPAD * 32) return;
    int row = i >> 5;
    float4 v = make_float4(0.f, 0.f, 0.f, 0.f);
    if (row < n) v = ((const float4*)x)[i];
    uint32_t h0, l0, h1, l1;
    split2(v.x, v.y, h0, l0);
    split2(v.z, v.w, h1, l1);
    ((uint2*)g_xh)[i] = make_uint2(h0, h1);
    ((uint2*)g_xl)[i] = make_uint2(l0, l1);
}

// ---------------- tensor-core GEMM: [hc | hl] = X @ [Wconv | Wlin] ----------
// CTA: 128 rows x 256 cols, 512 threads (16 warps, 4m x 4n warp grid).
#define OFF_AL 34816
#define OFF_B  69632
#define MMA_SMEM (OFF_B + 4 * 34816)   // 208896 bytes

__global__ void __launch_bounds__(512, 1)
k_mma(int layer, int nrows) {
    extern __shared__ char smc[];
    uint32_t sb = smem_u32(smc);
    int tid = threadIdx.x;
    int lane = tid & 31;
    int wid = tid >> 5;
    int row0 = blockIdx.x * 128;

    // ---- B copy: 4 images, contiguous 139264 B ----
    {
        const uint4* src = (const uint4*)(g_wb + (size_t)layer * 4 * WIMG);
        uint4* dst = (uint4*)(smc + OFF_B);
        #pragma unroll
        for (int t = tid; t < 8704; t += 512) dst[t] = src[t];
    }
    // ---- A copy: preformatted hi/lo planes (padded rows -> no bounds) ----
    {
        const uint4* sh = (const uint4*)g_xh + (size_t)row0 * 16;
        const uint4* sl = (const uint4*)g_xl + (size_t)row0 * 16;
        #pragma unroll
        for (int t = tid; t < 4096; t += 512) {
            int plane = t >> 11, r = (t >> 4) & 127, c = t & 15;
            const uint4* src = plane ? sl : sh;
            *(uint4*)(smc + plane * OFF_AL + r * (SA * 2) + c * 16) = src[r * 16 + c];
        }
    }
    __syncthreads();

    // ---- MMA mainloop ----
    int wr  = wid >> 2;
    int wc2 = wid & 3;
    int sel = wc2 >> 1;
    int nb64 = wc2 & 1;

    int arow = wr * 32 + (lane & 7) + ((lane & 8) ? 8 : 0);
    int akof = (lane & 16) ? 8 : 0;
    uint32_t aH = sb + (uint32_t)(arow * SA + akof) * 2;
    uint32_t aL = aH + OFF_AL;

    int brow = nb64 * 64 + (lane & 7);
    int bkof = (lane & 8) ? 8 : 0;
    uint32_t bH = sb + OFF_B + (uint32_t)sel * 69632 + (uint32_t)(brow * SA + bkof) * 2;
    uint32_t bL = bH + 34816;

    float c[2][8][4];
    #pragma unroll
    for (int i = 0; i < 2; i++)
        #pragma unroll
        for (int j = 0; j < 8; j++)
            #pragma unroll
            for (int q = 0; q < 4; q++) c[i][j][q] = 0.f;

    #pragma unroll
    for (int ks = 0; ks < 8; ks++) {
        uint32_t ka = ks * 32;
        uint32_t ah0[4], ah1[4], al0[4], al1[4];
        ldsm_x4(ah0, aH + ka);
        ldsm_x4(ah1, aH + ka + 16 * SA * 2);
        ldsm_x4(al0, aL + ka);
        ldsm_x4(al1, aL + ka + 16 * SA * 2);
        #pragma unroll
        for (int nt = 0; nt < 8; nt++) {
            uint32_t bh[2], bl[2];
            ldsm_x2(bh, bH + nt * (8 * SA * 2) + ka);
            ldsm_x2(bl, bL + nt * (8 * SA * 2) + ka);
            mma_bf16(c[0][nt], ah0, bh);
            mma_bf16(c[1][nt], ah1, bh);
            mma_bf16(c[0][nt], ah0, bl);
            mma_bf16(c[1][nt], ah1, bl);
            mma_bf16(c[0][nt], al0, bh);
            mma_bf16(c[1][nt], al1, bh);
        }
    }

    // ---- epilogue ----
    float* outp = sel ? g_hl : g_hc;
    int g  = lane >> 2;
    int tg = lane & 3;
    #pragma unroll
    for (int mt = 0; mt < 2; mt++) {
        int r0 = row0 + wr * 32 + mt * 16 + g;
        #pragma unroll
        for (int nt = 0; nt < 8; nt++) {
            int col = nb64 * 64 + nt * 8 + tg * 2;
            if (r0 < nrows)
                *(float2*)(outp + (size_t)r0 * 128 + col) =
                    make_float2(c[mt][nt][0], c[mt][nt][1]);
            if (r0 + 8 < nrows)
                *(float2*)(outp + (size_t)(r0 + 8) * 128 + col) =
                    make_float2(c[mt][nt][2], c[mt][nt][3]);
        }
    }
}

// ---------------- fused aggregate + bias + residual + LN + ReLU + JK --------
// layers 0,1: planes <- relu(LN(...)); xf accumulated in fp32.
// layer 2:    planes <- xf = g_xf + relu(LN(...)); g_xf not written.
__global__ void __launch_bounds__(256)
k_agg(const float* __restrict__ bconv, const float* __restrict__ blin,
      const float* __restrict__ lng, const float* __restrict__ lnb,
      int layer, int n) {
    int gwarp = (blockIdx.x * blockDim.x + threadIdx.x) >> 5;
    if (gwarp >= n) return;
    int lane = threadIdx.x & 31;
    int node = gwarp;

    float dn = g_dinv[node];
    const float4* HC = (const float4*)g_hc;
    const float4* HL = (const float4*)g_hl;

    float4 acc = make_float4(0.f, 0.f, 0.f, 0.f);
    int b = g_off[node], e = g_off[node + 1];
    int i = b;
    for (; i + 2 <= e; i += 2) {
        int s0 = g_srcs[i], s1 = g_srcs[i + 1];
        float w0 = g_wsc[i] * dn, w1 = g_wsc[i + 1] * dn;
        float4 h0 = HC[s0 * 32 + lane];
        float4 h1 = HC[s1 * 32 + lane];
        acc.x += h0.x * w0 + h1.x * w1;
        acc.y += h0.y * w0 + h1.y * w1;
        acc.z += h0.z * w0 + h1.z * w1;
        acc.w += h0.w * w0 + h1.w * w1;
    }
    if (i < e) {
        int s0 = g_srcs[i];
        float w0 = g_wsc[i] * dn;
        float4 h0 = HC[s0 * 32 + lane];
        acc.x += h0.x * w0; acc.y += h0.y * w0;
        acc.z += h0.z * w0; acc.w += h0.w * w0;
    }
    float sd = dn * dn;
    float4 hs = HC[node * 32 + lane];
    acc.x += hs.x * sd; acc.y += hs.y * sd; acc.z += hs.z * sd; acc.w += hs.w * sd;

    float4 hl4 = HL[node * 32 + lane];
    float4 bc  = ((const float4*)bconv)[lane];
    float4 bl  = ((const float4*)blin)[lane];
    float v0 = acc.x + bc.x + hl4.x + bl.x;
    float v1 = acc.y + bc.y + hl4.y + bl.y;
    float v2 = acc.z + bc.z + hl4.z + bl.z;
    float v3 = acc.w + bc.w + hl4.w + bl.w;

    float mu = wredsum(v0 + v1 + v2 + v3) * (1.0f / 128.0f);
    float d0 = v0 - mu, d1 = v1 - mu, d2 = v2 - mu, d3 = v3 - mu;
    float var = wredsum(d0 * d0 + d1 * d1 + d2 * d2 + d3 * d3) * (1.0f / 128.0f);
    float inv = rsqrtf(var + EPS);

    float4 g4 = ((const float4*)lng)[lane];
    float4 b4 = ((const float4*)lnb)[lane];
    v0 = fmaxf(0.f, d0 * inv * g4.x + b4.x);
    v1 = fmaxf(0.f, d1 * inv * g4.y + b4.y);
    v2 = fmaxf(0.f, d2 * inv * g4.z + b4.z);
    v3 = fmaxf(0.f, d3 * inv * g4.w + b4.w);

    float s0 = v0, s1 = v1, s2 = v2, s3 = v3;   // plane payload
    float4* XF = (float4*)g_xf;
    if (layer == 0) {
        XF[node * 32 + lane] = make_float4(v0, v1, v2, v3);
    } else {
        float4 r = XF[node * 32 + lane];
        if (layer == 1) {
            r.x += v0; r.y += v1; r.z += v2; r.w += v3;
            XF[node * 32 + lane] = r;
        } else {
            s0 = r.x + v0; s1 = r.y + v1; s2 = r.z + v2; s3 = r.w + v3;
        }
    }

    uint32_t h0, l0, h1, l1;
    split2(s0, s1, h0, l0);
    split2(s2, s3, h1, l1);
    ((uint2*)g_xh)[node * 32 + lane] = make_uint2(h0, h1);
    ((uint2*)g_xl)[node * 32 + lane] = make_uint2(l0, l1);
}

// ---------------- prediction GEMM via mma: out = xf @ Wpred + bpred ---------
// CTA: 128 rows x 64 cols (40 live), 256 threads (8 warps, 4m x 2n).
#define POFF_AL 34816
#define POFF_B  69632
#define PRED_SMEM (POFF_B + 2 * WIMGP * 2)   // 104448 bytes

__global__ void __launch_bounds__(256, 1)
k_predmma(const float* __restrict__ bp, float* __restrict__ out, int nrows) {
    extern __shared__ char smc[];
    uint32_t sb = smem_u32(smc);
    int tid = threadIdx.x;
    int lane = tid & 31;
    int wid = tid >> 5;
    int row0 = blockIdx.x * 128;

    // ---- B copy: hi+lo images, 34816 B ----
    {
        const uint4* src = (const uint4*)g_wbp;
        uint4* dst = (uint4*)(smc + POFF_B);
        #pragma unroll
        for (int t = tid; t < 2176; t += 256) dst[t] = src[t];
    }
    // ---- A copy ----
    {
        const uint4* sh = (const uint4*)g_xh + (size_t)row0 * 16;
        const uint4* sl = (const uint4*)g_xl + (size_t)row0 * 16;
        #pragma unroll
        for (int t = tid; t < 4096; t += 256) {
            int plane = t >> 11, r = (t >> 4) & 127, c = t & 15;
            const uint4* src = plane ? sl : sh;
            *(uint4*)(smc + plane * POFF_AL + r * (SA * 2) + c * 16) = src[r * 16 + c];
        }
    }
    __syncthreads();

    int wr = wid >> 1;            // warp row 0-3
    int wc = wid & 1;             // warp col 0-1 (32 cols each)

    int arow = wr * 32 + (lane & 7) + ((lane & 8) ? 8 : 0);
    int akof = (lane & 16) ? 8 : 0;
    uint32_t aH = sb + (uint32_t)(arow * SA + akof) * 2;
    uint32_t aL = aH + POFF_AL;

    int brow = wc * 32 + (lane & 7);
    int bkof = (lane & 8) ? 8 : 0;
    uint32_t bH = sb + POFF_B + (uint32_t)(brow * SA + bkof) * 2;
    uint32_t bL = bH + WIMGP * 2;

    float c[2][4][4];
    #pragma unroll
    for (int i = 0; i < 2; i++)
        #pragma unroll
        for (int j = 0; j < 4; j++)
            #pragma unroll
            for (int q = 0; q < 4; q++) c[i][j][q] = 0.f;

    #pragma unroll
    for (int ks = 0; ks < 8; ks++) {
        uint32_t ka = ks * 32;
        uint32_t ah0[4], ah1[4], al0[4], al1[4];
        ldsm_x4(ah0, aH + ka);
        ldsm_x4(ah1, aH + ka + 16 * SA * 2);
        ldsm_x4(al0, aL + ka);
        ldsm_x4(al1, aL + ka + 16 * SA * 2);
        #pragma unroll
        for (int nt = 0; nt < 4; nt++) {
            uint32_t bh[2], bl[2];
            ldsm_x2(bh, bH + nt * (8 * SA * 2) + ka);
            ldsm_x2(bl, bL + nt * (8 * SA * 2) + ka);
            mma_bf16(c[0][nt], ah0, bh);
            mma_bf16(c[1][nt], ah1, bh);
            mma_bf16(c[0][nt], ah0, bl);
            mma_bf16(c[1][nt], ah1, bl);
            mma_bf16(c[0][nt], al0, bh);
            mma_bf16(c[1][nt], al1, bh);
        }
    }

    int g  = lane >> 2;
    int tg = lane & 3;
    #pragma unroll
    for (int mt = 0; mt < 2; mt++) {
        int r0 = row0 + wr * 32 + mt * 16 + g;
        #pragma unroll
        for (int nt = 0; nt < 4; nt++) {
            int col = wc * 32 + nt * 8 + tg * 2;
            if (col < CC) {
                float b0 = bp[col], b1 = bp[col + 1];
                if (r0 < nrows)
                    *(float2*)(out + (size_t)r0 * CC + col) =
                        make_float2(c[mt][nt][0] + b0, c[mt][nt][1] + b1);
                if (r0 + 8 < nrows)
                    *(float2*)(out + (size_t)(r0 + 8) * CC + col) =
                        make_float2(c[mt][nt][2] + b0, c[mt][nt][3] + b1);
            }
        }
    }
}

// ---------------- launch ----------------
extern "C" void kernel_launch(void* const* d_in, const int* in_sizes, int n_in,
                              void* d_out, int out_size) {
    const float* x      = (const float*)d_in[0];
    const int*   ei     = (const int*)  d_in[1];
    const float* Wconv  = (const float*)d_in[2];
    const float* bconv  = (const float*)d_in[3];
    const float* Wlin   = (const float*)d_in[4];
    const float* blin   = (const float*)d_in[5];
    const float* ln_g   = (const float*)d_in[6];
    const float* ln_b   = (const float*)d_in[7];
    const float* Wpred  = (const float*)d_in[8];
    const float* bpred  = (const float*)d_in[9];
    float* out = (float*)d_out;

    int n = in_sizes[0] / DD;     // 50000
    int e = in_sizes[1] / 2;      // 600000

    static bool attr_set = false;
    if (!attr_set) {
        cudaFuncSetAttribute(k_mma, cudaFuncAttributeMaxDynamicSharedMemorySize,
                             MMA_SMEM);
        cudaFuncSetAttribute(k_predmma, cudaFuncAttributeMaxDynamicSharedMemorySize,
                             PRED_SMEM);
        attr_set = true;
    }

    int nb = (n + 1023) / 1024;

    k_deg <<<(e + 255) / 256, 256>>>(ei, e);
    k_scan1<<<nb, 1024>>>(n);
    k_scan3<<<nb, 1024>>>(n, e);
    k_place<<<(e + 255) / 256, 256>>>(ei, e);
    k_wprep<<<(LL * 128 * 128 + 64 * 128 + 255) / 256, 256>>>(Wconv, Wlin, Wpred);
    k_xprep<<<(NPAD * 32 + 255) / 256, 256>>>(x, n);

    int ntiles = (n + 127) / 128;
    for (int i = 0; i < LL; i++) {
        k_mma<<<ntiles, 512, MMA_SMEM>>>(i, n);
        k_agg<<<(n + 7) / 8, 256>>>(bconv + i * HH, blin + i * HH,
                                    ln_g + i * HH, ln_b + i * HH, i, n);
    }

    k_predmma<<<ntiles, 256, PRED_SMEM>>>(bpred, out, n);
}

// round 9
// speedup vs baseline: 1.6802x; 1.0207x over previous
#include <cuda_runtime.h>
#include <cuda_bf16.h>
#include <stdint.h>

// Problem constants (fixed by the dataset)
#define NN 50000
#define EE 600000
#define DD 128
#define HH 128
#define CC 40
#define LL 3
#define EPS 1e-5f

#define NPAD (((NN + 127) / 128) * 128)   // 50048 padded rows
#define SA 136                            // padded smem row stride (bf16 elems)
#define WIMG 17408                        // 128 * 136 bf16 per W image
#define WIMGP 8704                        // 64 * 136 bf16 per Wpred image

// ---------------- scratch (static __device__, no allocation) ----------------
__device__ float g_hc[NN * HH];           // x @ Wconv[i]
__device__ float g_hl[NN * HH];           // x @ Wlin[i]
__device__ float g_xf[NN * HH];           // JK sum (layers 0,1)
__device__ __nv_bfloat16 g_xh[NPAD * HH]; // activations / xf hi plane
__device__ __nv_bfloat16 g_xl[NPAD * HH]; // activations / xf lo plane
__device__ float g_dinv[NN];
__device__ int   g_cnt[NN];               // degree; restored to 0 by k_place
__device__ int   g_off[NN + 1];
__device__ int   g_part[128];
__device__ uint2 g_edge[EE];              // {src, bits(dinv[src])}
// Preformatted W: [layer][conv-hi, conv-lo, lin-hi, lin-lo][128n x 136k] bf16
__device__ __nv_bfloat16 g_wb[LL * 4 * WIMG];
// Preformatted Wpred: [hi, lo][64n x 136k] bf16 (rows 40-63 zero)
__device__ __nv_bfloat16 g_wbp[2 * WIMGP];

// ---------------- small PTX helpers ----------------
__device__ __forceinline__ uint32_t smem_u32(const void* p) {
    uint32_t a;
    asm("{ .reg .u64 t; cvta.to.shared.u64 t, %1; cvt.u32.u64 %0, t; }"
        : "=r"(a) : "l"(p));
    return a;
}
__device__ __forceinline__ void ldsm_x4(uint32_t* r, uint32_t addr) {
    asm volatile("ldmatrix.sync.aligned.m8n8.x4.shared.b16 {%0,%1,%2,%3}, [%4];"
        : "=r"(r[0]), "=r"(r[1]), "=r"(r[2]), "=r"(r[3]) : "r"(addr));
}
__device__ __forceinline__ void ldsm_x2(uint32_t* r, uint32_t addr) {
    asm volatile("ldmatrix.sync.aligned.m8n8.x2.shared.b16 {%0,%1}, [%2];"
        : "=r"(r[0]), "=r"(r[1]) : "r"(addr));
}
__device__ __forceinline__ void mma_bf16(float* c, const uint32_t* a,
                                         const uint32_t* b) {
    asm volatile("mma.sync.aligned.m16n8k16.row.col.f32.bf16.bf16.f32 "
                 "{%0,%1,%2,%3}, {%4,%5,%6,%7}, {%8,%9}, {%0,%1,%2,%3};"
                 : "+f"(c[0]), "+f"(c[1]), "+f"(c[2]), "+f"(c[3])
                 : "r"(a[0]), "r"(a[1]), "r"(a[2]), "r"(a[3]),
                   "r"(b[0]), "r"(b[1]));
}
__device__ __forceinline__ float wredsum(float v) {
    #pragma unroll
    for (int o = 16; o > 0; o >>= 1) v += __shfl_xor_sync(0xffffffffu, v, o);
    return v;
}
__device__ __forceinline__ int wredsumi(int v) {
    #pragma unroll
    for (int o = 16; o > 0; o >>= 1) v += __shfl_xor_sync(0xffffffffu, v, o);
    return v;
}
// hi/lo bf16 split pack: low half = first value
__device__ __forceinline__ void split2(float a, float b, uint32_t &hp, uint32_t &lp) {
    __nv_bfloat16 ha = __float2bfloat16(a);
    __nv_bfloat16 hb = __float2bfloat16(b);
    __nv_bfloat16 la = __float2bfloat16(a - __bfloat162float(ha));
    __nv_bfloat16 lb = __float2bfloat16(b - __bfloat162float(hb));
    hp = (uint32_t)__bfloat16_as_ushort(ha) | ((uint32_t)__bfloat16_as_ushort(hb) << 16);
    lp = (uint32_t)__bfloat16_as_ushort(la) | ((uint32_t)__bfloat16_as_ushort(lb) << 16);
}

// ---------------- preprocessing ----------------
__global__ void k_deg(const int* __restrict__ ei, int e) {
    int i = blockIdx.x * blockDim.x + threadIdx.x;
    if (i < e) atomicAdd(&g_cnt[ei[e + i]], 1);
}
// warp-shuffle block scan (1024 threads); also computes dinv
__global__ void k_scan1(int n) {
    __shared__ int ws[32];
    int t = threadIdx.x, idx = blockIdx.x * 1024 + t;
    int val = (idx < n) ? g_cnt[idx] : 0;
    if (idx < n) g_dinv[idx] = rsqrtf((float)val + 1.0f);
    int lane = t & 31, w = t >> 5;
    int inc = val;
    #pragma unroll
    for (int o = 1; o < 32; o <<= 1) {
        int u = __shfl_up_sync(0xffffffffu, inc, o);
        if (lane >= o) inc += u;
    }
    if (lane == 31) ws[w] = inc;
    __syncthreads();
    if (w == 0) {
        int s = ws[lane];
        int sc = s;
        #pragma unroll
        for (int o = 1; o < 32; o <<= 1) {
            int u = __shfl_up_sync(0xffffffffu, sc, o);
            if (lane >= o) sc += u;
        }
        ws[lane] = sc - s;
        if (lane == 31) g_part[blockIdx.x] = sc;
    }
    __syncthreads();
    if (idx < n) g_off[idx] = inc - val + ws[w];
}
// adds cross-block base (warp-reduced from g_part) and writes g_off[n]=e
__global__ void k_scan3(int n, int e) {
    __shared__ int base;
    int t = threadIdx.x;
    if (t < 32) {
        int s = 0;
        for (int j = t; j < blockIdx.x; j += 32) s += g_part[j];
        s = wredsumi(s);
        if (t == 0) base = s;
    }
    __syncthreads();
    int idx = blockIdx.x * 1024 + t;
    if (idx < n) g_off[idx] += base;
    if (blockIdx.x == 0 && t == 0) g_off[n] = e;
}
// slot via atomicSub on g_cnt -> g_cnt returns to all-zero afterwards
__global__ void k_place(const int* __restrict__ ei, int e) {
    int i = blockIdx.x * blockDim.x + threadIdx.x;
    if (i < e) {
        int s = ei[i];
        int d = ei[e + i];
        int p = g_off[d] + atomicSub(&g_cnt[d], 1) - 1;
        g_edge[p] = make_uint2((unsigned)s, __float_as_uint(g_dinv[s]));
    }
}

// ---------------- W preformat: fp32 -> bf16 hi/lo padded [n][k] images ------
__global__ void k_wprep(const float* __restrict__ Wconv,
                        const float* __restrict__ Wlin,
                        const float* __restrict__ Wpred) {
    int i = blockIdx.x * blockDim.x + threadIdx.x;
    if (i < LL * 128 * 128) {
        int l = i >> 14;
        int k = (i >> 7) & 127;
        int n = i & 127;
        float c = Wconv[l * 16384 + k * 128 + n];
        float v = Wlin [l * 16384 + k * 128 + n];
        int pos = n * SA + k;
        __nv_bfloat16 ch = __float2bfloat16(c);
        __nv_bfloat16 cl = __float2bfloat16(c - __bfloat162float(ch));
        __nv_bfloat16 vh = __float2bfloat16(v);
        __nv_bfloat16 vl = __float2bfloat16(v - __bfloat162float(vh));
        __nv_bfloat16* base = g_wb + (size_t)l * 4 * WIMG;
        base[0 * WIMG + pos] = ch;   // conv hi
        base[1 * WIMG + pos] = cl;   // conv lo
        base[2 * WIMG + pos] = vh;   // lin hi
        base[3 * WIMG + pos] = vl;   // lin lo
    } else if (i < LL * 128 * 128 + 64 * 128) {
        int j = i - LL * 128 * 128;
        int n = j >> 7;              // 0..63 output col
        int k = j & 127;
        float v = (n < CC) ? Wpred[k * CC + n] : 0.f;
        __nv_bfloat16 vh = __float2bfloat16(v);
        __nv_bfloat16 vl = __float2bfloat16(v - __bfloat162float(vh));
        int pos = n * SA + k;
        g_wbp[pos]         = vh;
        g_wbp[WIMGP + pos] = vl;
    }
}

// ---------------- layer-0 input: fp32 -> bf16 hi/lo planes (zero-padded) ----
__global__ void k_xprep(const float* __restrict__ x, int n) {
    int i = blockIdx.x * blockDim.x + threadIdx.x;
    if (i >= NPAD * 32) return;
    int row = i >> 5;
    float4 v = make_float4(0.f, 0.f, 0.f, 0.f);
    if (row < n) v = ((const float4*)x)[i];
    uint32_t h0, l0, h1, l1;
    split2(v.x, v.y, h0, l0);
    split2(v.z, v.w, h1, l1);
    ((uint2*)g_xh)[i] = make_uint2(h0, h1);
    ((uint2*)g_xl)[i] = make_uint2(l0, l1);
}

// ---------------- tensor-core GEMM: [hc | hl] = X @ [Wconv | Wlin] ----------
// CTA: 128 rows x 256 cols, 512 threads (16 warps, 4m x 4n warp grid).
#define OFF_AL 34816
#define OFF_B  69632
#define MMA_SMEM (OFF_B + 4 * 34816)   // 208896 bytes

__global__ void __launch_bounds__(512, 1)
k_mma(int layer, int nrows) {
    extern __shared__ char smc[];
    uint32_t sb = smem_u32(smc);
    int tid = threadIdx.x;
    int lane = tid & 31;
    int wid = tid >> 5;
    int row0 = blockIdx.x * 128;

    {
        const uint4* src = (const uint4*)(g_wb + (size_t)layer * 4 * WIMG);
        uint4* dst = (uint4*)(smc + OFF_B);
        #pragma unroll
        for (int t = tid; t < 8704; t += 512) dst[t] = src[t];
    }
    {
        const uint4* sh = (const uint4*)g_xh + (size_t)row0 * 16;
        const uint4* sl = (const uint4*)g_xl + (size_t)row0 * 16;
        #pragma unroll
        for (int t = tid; t < 4096; t += 512) {
            int plane = t >> 11, r = (t >> 4) & 127, c = t & 15;
            const uint4* src = plane ? sl : sh;
            *(uint4*)(smc + plane * OFF_AL + r * (SA * 2) + c * 16) = src[r * 16 + c];
        }
    }
    __syncthreads();

    int wr  = wid >> 2;
    int wc2 = wid & 3;
    int sel = wc2 >> 1;
    int nb64 = wc2 & 1;

    int arow = wr * 32 + (lane & 7) + ((lane & 8) ? 8 : 0);
    int akof = (lane & 16) ? 8 : 0;
    uint32_t aH = sb + (uint32_t)(arow * SA + akof) * 2;
    uint32_t aL = aH + OFF_AL;

    int brow = nb64 * 64 + (lane & 7);
    int bkof = (lane & 8) ? 8 : 0;
    uint32_t bH = sb + OFF_B + (uint32_t)sel * 69632 + (uint32_t)(brow * SA + bkof) * 2;
    uint32_t bL = bH + 34816;

    float c[2][8][4];
    #pragma unroll
    for (int i = 0; i < 2; i++)
        #pragma unroll
        for (int j = 0; j < 8; j++)
            #pragma unroll
            for (int q = 0; q < 4; q++) c[i][j][q] = 0.f;

    #pragma unroll
    for (int ks = 0; ks < 8; ks++) {
        uint32_t ka = ks * 32;
        uint32_t ah0[4], ah1[4], al0[4], al1[4];
        ldsm_x4(ah0, aH + ka);
        ldsm_x4(ah1, aH + ka + 16 * SA * 2);
        ldsm_x4(al0, aL + ka);
        ldsm_x4(al1, aL + ka + 16 * SA * 2);
        #pragma unroll
        for (int nt = 0; nt < 8; nt++) {
            uint32_t bh[2], bl[2];
            ldsm_x2(bh, bH + nt * (8 * SA * 2) + ka);
            ldsm_x2(bl, bL + nt * (8 * SA * 2) + ka);
            mma_bf16(c[0][nt], ah0, bh);
            mma_bf16(c[1][nt], ah1, bh);
            mma_bf16(c[0][nt], ah0, bl);
            mma_bf16(c[1][nt], ah1, bl);
            mma_bf16(c[0][nt], al0, bh);
            mma_bf16(c[1][nt], al1, bh);
        }
    }

    float* outp = sel ? g_hl : g_hc;
    int g  = lane >> 2;
    int tg = lane & 3;
    #pragma unroll
    for (int mt = 0; mt < 2; mt++) {
        int r0 = row0 + wr * 32 + mt * 16 + g;
        #pragma unroll
        for (int nt = 0; nt < 8; nt++) {
            int col = nb64 * 64 + nt * 8 + tg * 2;
            if (r0 < nrows)
                *(float2*)(outp + (size_t)r0 * 128 + col) =
                    make_float2(c[mt][nt][0], c[mt][nt][1]);
            if (r0 + 8 < nrows)
                *(float2*)(outp + (size_t)(r0 + 8) * 128 + col) =
                    make_float2(c[mt][nt][2], c[mt][nt][3]);
        }
    }
}

// ---------------- fused aggregate + bias + residual + LN + ReLU + JK --------
__global__ void __launch_bounds__(256)
k_agg(const float* __restrict__ bconv, const float* __restrict__ blin,
      const float* __restrict__ lng, const float* __restrict__ lnb,
      int layer, int n) {
    int gwarp = (blockIdx.x * blockDim.x + threadIdx.x) >> 5;
    if (gwarp >= n) return;
    int lane = threadIdx.x & 31;
    int node = gwarp;

    float dn = g_dinv[node];
    const float4* HC = (const float4*)g_hc;
    const float4* HL = (const float4*)g_hl;
    const uint2* E = g_edge;

    float4 acc = make_float4(0.f, 0.f, 0.f, 0.f);
    int b = g_off[node], end = g_off[node + 1];
    int i = b;
    for (; i + 4 <= end; i += 4) {
        uint2 e0 = E[i], e1 = E[i + 1], e2 = E[i + 2], e3 = E[i + 3];
        float w0 = __uint_as_float(e0.y) * dn;
        float w1 = __uint_as_float(e1.y) * dn;
        float w2 = __uint_as_float(e2.y) * dn;
        float w3 = __uint_as_float(e3.y) * dn;
        float4 h0 = HC[e0.x * 32 + lane];
        float4 h1 = HC[e1.x * 32 + lane];
        float4 h2 = HC[e2.x * 32 + lane];
        float4 h3 = HC[e3.x * 32 + lane];
        acc.x += h0.x * w0 + h1.x * w1 + h2.x * w2 + h3.x * w3;
        acc.y += h0.y * w0 + h1.y * w1 + h2.y * w2 + h3.y * w3;
        acc.z += h0.z * w0 + h1.z * w1 + h2.z * w2 + h3.z * w3;
        acc.w += h0.w * w0 + h1.w * w1 + h2.w * w2 + h3.w * w3;
    }
    for (; i < end; i++) {
        uint2 e0 = E[i];
        float w0 = __uint_as_float(e0.y) * dn;
        float4 h0 = HC[e0.x * 32 + lane];
        acc.x += h0.x * w0; acc.y += h0.y * w0;
        acc.z += h0.z * w0; acc.w += h0.w * w0;
    }
    float sd = dn * dn;
    float4 hs = HC[node * 32 + lane];
    acc.x += hs.x * sd; acc.y += hs.y * sd; acc.z += hs.z * sd; acc.w += hs.w * sd;

    float4 hl4 = HL[node * 32 + lane];
    float4 bc  = ((const float4*)bconv)[lane];
    float4 bl  = ((const float4*)blin)[lane];
    float v0 = acc.x + bc.x + hl4.x + bl.x;
    float v1 = acc.y + bc.y + hl4.y + bl.y;
    float v2 = acc.z + bc.z + hl4.z + bl.z;
    float v3 = acc.w + bc.w + hl4.w + bl.w;

    float mu = wredsum(v0 + v1 + v2 + v3) * (1.0f / 128.0f);
    float d0 = v0 - mu, d1 = v1 - mu, d2 = v2 - mu, d3 = v3 - mu;
    float var = wredsum(d0 * d0 + d1 * d1 + d2 * d2 + d3 * d3) * (1.0f / 128.0f);
    float inv = rsqrtf(var + EPS);

    float4 g4 = ((const float4*)lng)[lane];
    float4 b4 = ((const float4*)lnb)[lane];
    v0 = fmaxf(0.f, d0 * inv * g4.x + b4.x);
    v1 = fmaxf(0.f, d1 * inv * g4.y + b4.y);
    v2 = fmaxf(0.f, d2 * inv * g4.z + b4.z);
    v3 = fmaxf(0.f, d3 * inv * g4.w + b4.w);

    float s0 = v0, s1 = v1, s2 = v2, s3 = v3;
    float4* XF = (float4*)g_xf;
    if (layer == 0) {
        XF[node * 32 + lane] = make_float4(v0, v1, v2, v3);
    } else {
        float4 r = XF[node * 32 + lane];
        if (layer == 1) {
            r.x += v0; r.y += v1; r.z += v2; r.w += v3;
            XF[node * 32 + lane] = r;
        } else {
            s0 = r.x + v0; s1 = r.y + v1; s2 = r.z + v2; s3 = r.w + v3;
        }
    }

    uint32_t h0, l0, h1, l1;
    split2(s0, s1, h0, l0);
    split2(s2, s3, h1, l1);
    ((uint2*)g_xh)[node * 32 + lane] = make_uint2(h0, h1);
    ((uint2*)g_xl)[node * 32 + lane] = make_uint2(l0, l1);
}

// ---------------- prediction GEMM via mma: out = xf @ Wpred + bpred ---------
#define POFF_AL 34816
#define POFF_B  69632
#define PRED_SMEM (POFF_B + 2 * WIMGP * 2)   // 104448 bytes

__global__ void __launch_bounds__(256, 1)
k_predmma(const float* __restrict__ bp, float* __restrict__ out, int nrows) {
    extern __shared__ char smc[];
    uint32_t sb = smem_u32(smc);
    int tid = threadIdx.x;
    int lane = tid & 31;
    int wid = tid >> 5;
    int row0 = blockIdx.x * 128;

    {
        const uint4* src = (const uint4*)g_wbp;
        uint4* dst = (uint4*)(smc + POFF_B);
        #pragma unroll
        for (int t = tid; t < 2176; t += 256) dst[t] = src[t];
    }
    {
        const uint4* sh = (const uint4*)g_xh + (size_t)row0 * 16;
        const uint4* sl = (const uint4*)g_xl + (size_t)row0 * 16;
        #pragma unroll
        for (int t = tid; t < 4096; t += 256) {
            int plane = t >> 11, r = (t >> 4) & 127, c = t & 15;
            const uint4* src = plane ? sl : sh;
            *(uint4*)(smc + plane * POFF_AL + r * (SA * 2) + c * 16) = src[r * 16 + c];
        }
    }
    __syncthreads();

    int wr = wid >> 1;
    int wc = wid & 1;

    int arow = wr * 32 + (lane & 7) + ((lane & 8) ? 8 : 0);
    int akof = (lane & 16) ? 8 : 0;
    uint32_t aH = sb + (uint32_t)(arow * SA + akof) * 2;
    uint32_t aL = aH + POFF_AL;

    int brow = wc * 32 + (lane & 7);
    int bkof = (lane & 8) ? 8 : 0;
    uint32_t bH = sb + POFF_B + (uint32_t)(brow * SA + bkof) * 2;
    uint32_t bL = bH + WIMGP * 2;

    float c[2][4][4];
    #pragma unroll
    for (int i = 0; i < 2; i++)
        #pragma unroll
        for (int j = 0; j < 4; j++)
            #pragma unroll
            for (int q = 0; q < 4; q++) c[i][j][q] = 0.f;

    #pragma unroll
    for (int ks = 0; ks < 8; ks++) {
        uint32_t ka = ks * 32;
        uint32_t ah0[4], ah1[4], al0[4], al1[4];
        ldsm_x4(ah0, aH + ka);
        ldsm_x4(ah1, aH + ka + 16 * SA * 2);
        ldsm_x4(al0, aL + ka);
        ldsm_x4(al1, aL + ka + 16 * SA * 2);
        #pragma unroll
        for (int nt = 0; nt < 4; nt++) {
            uint32_t bh[2], bl[2];
            ldsm_x2(bh, bH + nt * (8 * SA * 2) + ka);
            ldsm_x2(bl, bL + nt * (8 * SA * 2) + ka);
            mma_bf16(c[0][nt], ah0, bh);
            mma_bf16(c[1][nt], ah1, bh);
            mma_bf16(c[0][nt], ah0, bl);
            mma_bf16(c[1][nt], ah1, bl);
            mma_bf16(c[0][nt], al0, bh);
            mma_bf16(c[1][nt], al1, bh);
        }
    }

    int g  = lane >> 2;
    int tg = lane & 3;
    #pragma unroll
    for (int mt = 0; mt < 2; mt++) {
        int r0 = row0 + wr * 32 + mt * 16 + g;
        #pragma unroll
        for (int nt = 0; nt < 4; nt++) {
            int col = wc * 32 + nt * 8 + tg * 2;
            if (col < CC) {
                float b0 = bp[col], b1 = bp[col + 1];
                if (r0 < nrows)
                    *(float2*)(out + (size_t)r0 * CC + col) =
                        make_float2(c[mt][nt][0] + b0, c[mt][nt][1] + b1);
                if (r0 + 8 < nrows)
                    *(float2*)(out + (size_t)(r0 + 8) * CC + col) =
                        make_float2(c[mt][nt][2] + b0, c[mt][nt][3] + b1);
            }
        }
    }
}

// ---------------- launch ----------------
extern "C" void kernel_launch(void* const* d_in, const int* in_sizes, int n_in,
                              void* d_out, int out_size) {
    const float* x      = (const float*)d_in[0];
    const int*   ei     = (const int*)  d_in[1];
    const float* Wconv  = (const float*)d_in[2];
    const float* bconv  = (const float*)d_in[3];
    const float* Wlin   = (const float*)d_in[4];
    const float* blin   = (const float*)d_in[5];
    const float* ln_g   = (const float*)d_in[6];
    const float* ln_b   = (const float*)d_in[7];
    const float* Wpred  = (const float*)d_in[8];
    const float* bpred  = (const float*)d_in[9];
    float* out = (float*)d_out;

    int n = in_sizes[0] / DD;     // 50000
    int e = in_sizes[1] / 2;      // 600000

    static bool attr_set = false;
    if (!attr_set) {
        cudaFuncSetAttribute(k_mma, cudaFuncAttributeMaxDynamicSharedMemorySize,
                             MMA_SMEM);
        cudaFuncSetAttribute(k_predmma, cudaFuncAttributeMaxDynamicSharedMemorySize,
                             PRED_SMEM);
        attr_set = true;
    }

    int nb = (n + 1023) / 1024;

    k_deg  <<<(e + 255) / 256, 256>>>(ei, e);
    k_scan1<<<nb, 1024>>>(n);
    k_scan3<<<nb, 1024>>>(n, e);
    k_place<<<(e + 255) / 256, 256>>>(ei, e);
    k_wprep<<<(LL * 128 * 128 + 64 * 128 + 255) / 256, 256>>>(Wconv, Wlin, Wpred);
    k_xprep<<<(NPAD * 32 + 255) / 256, 256>>>(x, n);

    int ntiles = (n + 127) / 128;
    for (int i = 0; i < LL; i++) {
        k_mma<<<ntiles, 512, MMA_SMEM>>>(i, n);
        k_agg<<<(n + 7) / 8, 256>>>(bconv + i * HH, blin + i * HH,
                                    ln_g + i * HH, ln_b + i * HH, i, n);
    }

    k_predmma<<<ntiles, 256, PRED_SMEM>>>(bpred, out, n);
}

// round 10
// speedup vs baseline: 1.8863x; 1.1227x over previous
#include <cuda_runtime.h>
#include <cuda_bf16.h>
#include <stdint.h>

// Problem constants (fixed by the dataset)
#define NN 50000
#define EE 600000
#define DD 128
#define HH 128
#define CC 40
#define LL 3
#define EPS 1e-5f

#define NPAD (((NN + 127) / 128) * 128)   // 50048 padded rows
#define SA 136                            // padded smem row stride (bf16 elems)
#define WIMG 17408                        // 128 * 136 bf16 per W image
#define WIMGP 8704                        // 64 * 136 bf16 per Wpred image
#define NWP (LL * 128 * 128)              // 49152 conv/lin wprep items
#define NWTOT (NWP + 64 * 128)            // + pred wprep items = 57344

// ---------------- scratch (static __device__, no allocation) ----------------
__device__ float g_hc[NN * HH];           // dinv-scaled x @ Wconv[i]
__device__ float g_hl[NN * HH];           // x @ Wlin[i]
__device__ float g_xf[NN * HH];           // JK sum (layers 0,1)
__device__ __nv_bfloat16 g_xh[NPAD * HH]; // activations / xf hi plane
__device__ __nv_bfloat16 g_xl[NPAD * HH]; // activations / xf lo plane
__device__ float g_dinv[NN];
__device__ int   g_cnt[NN];               // degree histogram; zeroed by k_scan1
__device__ int   g_off[NN + 1];
__device__ int   g_pos[NN];               // placement cursor = off[i]+deg[i]
__device__ int   g_part[128];
__device__ int   g_src[EE];               // CSR src indices
// Preformatted W: [layer][conv-hi, conv-lo, lin-hi, lin-lo][128n x 136k] bf16
__device__ __nv_bfloat16 g_wb[LL * 4 * WIMG];
// Preformatted Wpred: [hi, lo][64n x 136k] bf16 (rows 40-63 zero)
__device__ __nv_bfloat16 g_wbp[2 * WIMGP];

// ---------------- small PTX helpers ----------------
__device__ __forceinline__ uint32_t smem_u32(const void* p) {
    uint32_t a;
    asm("{ .reg .u64 t; cvta.to.shared.u64 t, %1; cvt.u32.u64 %0, t; }"
        : "=r"(a) : "l"(p));
    return a;
}
__device__ __forceinline__ void ldsm_x4(uint32_t* r, uint32_t addr) {
    asm volatile("ldmatrix.sync.aligned.m8n8.x4.shared.b16 {%0,%1,%2,%3}, [%4];"
        : "=r"(r[0]), "=r"(r[1]), "=r"(r[2]), "=r"(r[3]) : "r"(addr));
}
__device__ __forceinline__ void ldsm_x2(uint32_t* r, uint32_t addr) {
    asm volatile("ldmatrix.sync.aligned.m8n8.x2.shared.b16 {%0,%1}, [%2];"
        : "=r"(r[0]), "=r"(r[1]) : "r"(addr));
}
__device__ __forceinline__ void mma_bf16(float* c, const uint32_t* a,
                                         const uint32_t* b) {
    asm volatile("mma.sync.aligned.m16n8k16.row.col.f32.bf16.bf16.f32 "
                 "{%0,%1,%2,%3}, {%4,%5,%6,%7}, {%8,%9}, {%0,%1,%2,%3};"
                 : "+f"(c[0]), "+f"(c[1]), "+f"(c[2]), "+f"(c[3])
                 : "r"(a[0]), "r"(a[1]), "r"(a[2]), "r"(a[3]),
                   "r"(b[0]), "r"(b[1]));
}
__device__ __forceinline__ float wredsum(float v) {
    #pragma unroll
    for (int o = 16; o > 0; o >>= 1) v += __shfl_xor_sync(0xffffffffu, v, o);
    return v;
}
__device__ __forceinline__ int wredsumi(int v) {
    #pragma unroll
    for (int o = 16; o > 0; o >>= 1) v += __shfl_xor_sync(0xffffffffu, v, o);
    return v;
}
// hi/lo bf16 split pack: low half = first value
__device__ __forceinline__ void split2(float a, float b, uint32_t &hp, uint32_t &lp) {
    __nv_bfloat16 ha = __float2bfloat16(a);
    __nv_bfloat16 hb = __float2bfloat16(b);
    __nv_bfloat16 la = __float2bfloat16(a - __bfloat162float(ha));
    __nv_bfloat16 lb = __float2bfloat16(b - __bfloat162float(hb));
    hp = (uint32_t)__bfloat16_as_ushort(ha) | ((uint32_t)__bfloat16_as_ushort(hb) << 16);
    lp = (uint32_t)__bfloat16_as_ushort(la) | ((uint32_t)__bfloat16_as_ushort(lb) << 16);
}

// ---------------- preprocessing ----------------
__global__ void k_deg(const int* __restrict__ ei, int e) {
    int i = blockIdx.x * blockDim.x + threadIdx.x;
    if (i < e) atomicAdd(&g_cnt[ei[e + i]], 1);
}
// warp-shuffle block scan; also computes dinv, zeroes g_cnt, seeds g_pos
__global__ void k_scan1(int n) {
    __shared__ int ws[32];
    int t = threadIdx.x, idx = blockIdx.x * 1024 + t;
    int val = (idx < n) ? g_cnt[idx] : 0;
    if (idx < n) {
        g_dinv[idx] = rsqrtf((float)val + 1.0f);
        g_cnt[idx] = 0;                      // ready for next replay
    }
    int lane = t & 31, w = t >> 5;
    int inc = val;
    #pragma unroll
    for (int o = 1; o < 32; o <<= 1) {
        int u = __shfl_up_sync(0xffffffffu, inc, o);
        if (lane >= o) inc += u;
    }
    if (lane == 31) ws[w] = inc;
    __syncthreads();
    if (w == 0) {
        int s = ws[lane];
        int sc = s;
        #pragma unroll
        for (int o = 1; o < 32; o <<= 1) {
            int u = __shfl_up_sync(0xffffffffu, sc, o);
            if (lane >= o) sc += u;
        }
        ws[lane] = sc - s;
        if (lane == 31) g_part[blockIdx.x] = sc;
    }
    __syncthreads();
    if (idx < n) {
        int excl = inc - val + ws[w];
        g_off[idx] = excl;
        g_pos[idx] = excl + val;             // inclusive = placement cursor
    }
}
// adds cross-block base to g_off and g_pos; writes g_off[n]=e
__global__ void k_scan3(int n, int e) {
    __shared__ int base;
    int t = threadIdx.x;
    if (t < 32) {
        int s = 0;
        for (int j = t; j < blockIdx.x; j += 32) s += g_part[j];
        s = wredsumi(s);
        if (t == 0) base = s;
    }
    __syncthreads();
    int idx = blockIdx.x * 1024 + t;
    if (idx < n) { g_off[idx] += base; g_pos[idx] += base; }
    if (blockIdx.x == 0 && t == 0) g_off[n] = e;
}
// slot via atomicSub on g_pos; stores only src (4 B)
__global__ void k_place(const int* __restrict__ ei, int e) {
    int i = blockIdx.x * blockDim.x + threadIdx.x;
    if (i < e) {
        int s = ei[i];
        int d = ei[e + i];
        int p = atomicSub(&g_pos[d], 1) - 1;
        g_src[p] = s;
    }
}

// ---------------- merged prep: W images + layer-0 input planes --------------
__global__ void k_prep(const float* __restrict__ Wconv,
                       const float* __restrict__ Wlin,
                       const float* __restrict__ Wpred,
                       const float* __restrict__ x, int n) {
    int i = blockIdx.x * blockDim.x + threadIdx.x;
    if (i < NWP) {
        int l = i >> 14;
        int k = (i >> 7) & 127;
        int nn = i & 127;
        float c = Wconv[l * 16384 + k * 128 + nn];
        float v = Wlin [l * 16384 + k * 128 + nn];
        int pos = nn * SA + k;
        __nv_bfloat16 ch = __float2bfloat16(c);
        __nv_bfloat16 cl = __float2bfloat16(c - __bfloat162float(ch));
        __nv_bfloat16 vh = __float2bfloat16(v);
        __nv_bfloat16 vl = __float2bfloat16(v - __bfloat162float(vh));
        __nv_bfloat16* base = g_wb + (size_t)l * 4 * WIMG;
        base[0 * WIMG + pos] = ch;
        base[1 * WIMG + pos] = cl;
        base[2 * WIMG + pos] = vh;
        base[3 * WIMG + pos] = vl;
    } else if (i < NWTOT) {
        int j = i - NWP;
        int nn = j >> 7;
        int k = j & 127;
        float v = (nn < CC) ? Wpred[k * CC + nn] : 0.f;
        __nv_bfloat16 vh = __float2bfloat16(v);
        __nv_bfloat16 vl = __float2bfloat16(v - __bfloat162float(vh));
        int pos = nn * SA + k;
        g_wbp[pos]         = vh;
        g_wbp[WIMGP + pos] = vl;
    } else {
        int j = i - NWTOT;
        if (j >= NPAD * 32) return;
        int row = j >> 5;
        float4 v = make_float4(0.f, 0.f, 0.f, 0.f);
        if (row < n) v = ((const float4*)x)[j];
        uint32_t h0, l0, h1, l1;
        split2(v.x, v.y, h0, l0);
        split2(v.z, v.w, h1, l1);
        ((uint2*)g_xh)[j] = make_uint2(h0, h1);
        ((uint2*)g_xl)[j] = make_uint2(l0, l1);
    }
}

// ---------------- tensor-core GEMM: [hc' | hl] = X @ [Wconv | Wlin] ---------
// hc' = dinv-scaled conv product. CTA: 128 rows x 256 cols, 512 threads.
#define OFF_AL 34816
#define OFF_B  69632
#define MMA_SMEM (OFF_B + 4 * 34816)   // 208896 bytes

__global__ void __launch_bounds__(512, 1)
k_mma(int layer, int nrows) {
    extern __shared__ char smc[];
    uint32_t sb = smem_u32(smc);
    int tid = threadIdx.x;
    int lane = tid & 31;
    int wid = tid >> 5;
    int row0 = blockIdx.x * 128;

    {
        const uint4* src = (const uint4*)(g_wb + (size_t)layer * 4 * WIMG);
        uint4* dst = (uint4*)(smc + OFF_B);
        #pragma unroll
        for (int t = tid; t < 8704; t += 512) dst[t] = src[t];
    }
    {
        const uint4* sh = (const uint4*)g_xh + (size_t)row0 * 16;
        const uint4* sl = (const uint4*)g_xl + (size_t)row0 * 16;
        #pragma unroll
        for (int t = tid; t < 4096; t += 512) {
            int plane = t >> 11, r = (t >> 4) & 127, c = t & 15;
            const uint4* src = plane ? sl : sh;
            *(uint4*)(smc + plane * OFF_AL + r * (SA * 2) + c * 16) = src[r * 16 + c];
        }
    }
    __syncthreads();

    int wr  = wid >> 2;
    int wc2 = wid & 3;
    int sel = wc2 >> 1;
    int nb64 = wc2 & 1;

    int arow = wr * 32 + (lane & 7) + ((lane & 8) ? 8 : 0);
    int akof = (lane & 16) ? 8 : 0;
    uint32_t aH = sb + (uint32_t)(arow * SA + akof) * 2;
    uint32_t aL = aH + OFF_AL;

    int brow = nb64 * 64 + (lane & 7);
    int bkof = (lane & 8) ? 8 : 0;
    uint32_t bH = sb + OFF_B + (uint32_t)sel * 69632 + (uint32_t)(brow * SA + bkof) * 2;
    uint32_t bL = bH + 34816;

    float c[2][8][4];
    #pragma unroll
    for (int i = 0; i < 2; i++)
        #pragma unroll
        for (int j = 0; j < 8; j++)
            #pragma unroll
            for (int q = 0; q < 4; q++) c[i][j][q] = 0.f;

    #pragma unroll
    for (int ks = 0; ks < 8; ks++) {
        uint32_t ka = ks * 32;
        uint32_t ah0[4], ah1[4], al0[4], al1[4];
        ldsm_x4(ah0, aH + ka);
        ldsm_x4(ah1, aH + ka + 16 * SA * 2);
        ldsm_x4(al0, aL + ka);
        ldsm_x4(al1, aL + ka + 16 * SA * 2);
        #pragma unroll
        for (int nt = 0; nt < 8; nt++) {
            uint32_t bh[2], bl[2];
            ldsm_x2(bh, bH + nt * (8 * SA * 2) + ka);
            ldsm_x2(bl, bL + nt * (8 * SA * 2) + ka);
            mma_bf16(c[0][nt], ah0, bh);
            mma_bf16(c[1][nt], ah1, bh);
            mma_bf16(c[0][nt], ah0, bl);
            mma_bf16(c[1][nt], ah1, bl);
            mma_bf16(c[0][nt], al0, bh);
            mma_bf16(c[1][nt], al1, bh);
        }
    }

    float* outp = sel ? g_hl : g_hc;
    int g  = lane >> 2;
    int tg = lane & 3;
    #pragma unroll
    for (int mt = 0; mt < 2; mt++) {
        int r0 = row0 + wr * 32 + mt * 16 + g;
        float sc0 = 1.f, sc1 = 1.f;
        if (sel == 0) {
            if (r0 < nrows)     sc0 = g_dinv[r0];
            if (r0 + 8 < nrows) sc1 = g_dinv[r0 + 8];
        }
        #pragma unroll
        for (int nt = 0; nt < 8; nt++) {
            int col = nb64 * 64 + nt * 8 + tg * 2;
            if (r0 < nrows)
                *(float2*)(outp + (size_t)r0 * 128 + col) =
                    make_float2(c[mt][nt][0] * sc0, c[mt][nt][1] * sc0);
            if (r0 + 8 < nrows)
                *(float2*)(outp + (size_t)(r0 + 8) * 128 + col) =
                    make_float2(c[mt][nt][2] * sc1, c[mt][nt][3] * sc1);
        }
    }
}

// ---------------- fused aggregate + bias + residual + LN + ReLU + JK --------
// conv = dn * (sum_src HC'[src] + HC'[node]) since HC' is dinv-prescaled.
__global__ void __launch_bounds__(256)
k_agg(const float* __restrict__ bconv, const float* __restrict__ blin,
      const float* __restrict__ lng, const float* __restrict__ lnb,
      int layer, int n) {
    int gwarp = (blockIdx.x * blockDim.x + threadIdx.x) >> 5;
    if (gwarp >= n) return;
    int lane = threadIdx.x & 31;
    int node = gwarp;

    float dn = g_dinv[node];
    const float4* HC = (const float4*)g_hc;
    const float4* HL = (const float4*)g_hl;
    const int* S = g_src;

    float4 acc = make_float4(0.f, 0.f, 0.f, 0.f);
    int b = g_off[node], end = g_off[node + 1];
    int i = b;
    for (; i + 4 <= end; i += 4) {
        int s0 = S[i], s1 = S[i + 1], s2 = S[i + 2], s3 = S[i + 3];
        float4 h0 = HC[s0 * 32 + lane];
        float4 h1 = HC[s1 * 32 + lane];
        float4 h2 = HC[s2 * 32 + lane];
        float4 h3 = HC[s3 * 32 + lane];
        acc.x += (h0.x + h1.x) + (h2.x + h3.x);
        acc.y += (h0.y + h1.y) + (h2.y + h3.y);
        acc.z += (h0.z + h1.z) + (h2.z + h3.z);
        acc.w += (h0.w + h1.w) + (h2.w + h3.w);
    }
    for (; i < end; i++) {
        float4 h0 = HC[S[i] * 32 + lane];
        acc.x += h0.x; acc.y += h0.y; acc.z += h0.z; acc.w += h0.w;
    }
    float4 hs = HC[node * 32 + lane];      // self loop (already dinv-scaled)
    acc.x += hs.x; acc.y += hs.y; acc.z += hs.z; acc.w += hs.w;

    float4 hl4 = HL[node * 32 + lane];
    float4 bc  = ((const float4*)bconv)[lane];
    float4 bl  = ((const float4*)blin)[lane];
    float v0 = acc.x * dn + bc.x + hl4.x + bl.x;
    float v1 = acc.y * dn + bc.y + hl4.y + bl.y;
    float v2 = acc.z * dn + bc.z + hl4.z + bl.z;
    float v3 = acc.w * dn + bc.w + hl4.w + bl.w;

    float mu = wredsum(v0 + v1 + v2 + v3) * (1.0f / 128.0f);
    float d0 = v0 - mu, d1 = v1 - mu, d2 = v2 - mu, d3 = v3 - mu;
    float var = wredsum(d0 * d0 + d1 * d1 + d2 * d2 + d3 * d3) * (1.0f / 128.0f);
    float inv = rsqrtf(var + EPS);

    float4 g4 = ((const float4*)lng)[lane];
    float4 b4 = ((const float4*)lnb)[lane];
    v0 = fmaxf(0.f, d0 * inv * g4.x + b4.x);
    v1 = fmaxf(0.f, d1 * inv * g4.y + b4.y);
    v2 = fmaxf(0.f, d2 * inv * g4.z + b4.z);
    v3 = fmaxf(0.f, d3 * inv * g4.w + b4.w);

    float s0 = v0, s1 = v1, s2 = v2, s3 = v3;
    float4* XF = (float4*)g_xf;
    if (layer == 0) {
        XF[node * 32 + lane] = make_float4(v0, v1, v2, v3);
    } else {
        float4 r = XF[node * 32 + lane];
        if (layer == 1) {
            r.x += v0; r.y += v1; r.z += v2; r.w += v3;
            XF[node * 32 + lane] = r;
        } else {
            s0 = r.x + v0; s1 = r.y + v1; s2 = r.z + v2; s3 = r.w + v3;
        }
    }

    uint32_t h0, l0, h1, l1;
    split2(s0, s1, h0, l0);
    split2(s2, s3, h1, l1);
    ((uint2*)g_xh)[node * 32 + lane] = make_uint2(h0, h1);
    ((uint2*)g_xl)[node * 32 + lane] = make_uint2(l0, l1);
}

// ---------------- prediction GEMM via mma: out = xf @ Wpred + bpred ---------
#define POFF_AL 34816
#define POFF_B  69632
#define PRED_SMEM (POFF_B + 2 * WIMGP * 2)   // 104448 bytes

__global__ void __launch_bounds__(256, 1)
k_predmma(const float* __restrict__ bp, float* __restrict__ out, int nrows) {
    extern __shared__ char smc[];
    uint32_t sb = smem_u32(smc);
    int tid = threadIdx.x;
    int lane = tid & 31;
    int wid = tid >> 5;
    int row0 = blockIdx.x * 128;

    {
        const uint4* src = (const uint4*)g_wbp;
        uint4* dst = (uint4*)(smc + POFF_B);
        #pragma unroll
        for (int t = tid; t < 2176; t += 256) dst[t] = src[t];
    }
    {
        const uint4* sh = (const uint4*)g_xh + (size_t)row0 * 16;
        const uint4* sl = (const uint4*)g_xl + (size_t)row0 * 16;
        #pragma unroll
        for (int t = tid; t < 4096; t += 256) {
            int plane = t >> 11, r = (t >> 4) & 127, c = t & 15;
            const uint4* src = plane ? sl : sh;
            *(uint4*)(smc + plane * POFF_AL + r * (SA * 2) + c * 16) = src[r * 16 + c];
        }
    }
    __syncthreads();

    int wr = wid >> 1;
    int wc = wid & 1;

    int arow = wr * 32 + (lane & 7) + ((lane & 8) ? 8 : 0);
    int akof = (lane & 16) ? 8 : 0;
    uint32_t aH = sb + (uint32_t)(arow * SA + akof) * 2;
    uint32_t aL = aH + POFF_AL;

    int brow = wc * 32 + (lane & 7);
    int bkof = (lane & 8) ? 8 : 0;
    uint32_t bH = sb + POFF_B + (uint32_t)(brow * SA + bkof) * 2;
    uint32_t bL = bH + WIMGP * 2;

    float c[2][4][4];
    #pragma unroll
    for (int i = 0; i < 2; i++)
        #pragma unroll
        for (int j = 0; j < 4; j++)
            #pragma unroll
            for (int q = 0; q < 4; q++) c[i][j][q] = 0.f;

    #pragma unroll
    for (int ks = 0; ks < 8; ks++) {
        uint32_t ka = ks * 32;
        uint32_t ah0[4], ah1[4], al0[4], al1[4];
        ldsm_x4(ah0, aH + ka);
        ldsm_x4(ah1, aH + ka + 16 * SA * 2);
        ldsm_x4(al0, aL + ka);
        ldsm_x4(al1, aL + ka + 16 * SA * 2);
        #pragma unroll
        for (int nt = 0; nt < 4; nt++) {
            uint32_t bh[2], bl[2];
            ldsm_x2(bh, bH + nt * (8 * SA * 2) + ka);
            ldsm_x2(bl, bL + nt * (8 * SA * 2) + ka);
            mma_bf16(c[0][nt], ah0, bh);
            mma_bf16(c[1][nt], ah1, bh);
            mma_bf16(c[0][nt], ah0, bl);
            mma_bf16(c[1][nt], ah1, bl);
            mma_bf16(c[0][nt], al0, bh);
            mma_bf16(c[1][nt], al1, bh);
        }
    }

    int g  = lane >> 2;
    int tg = lane & 3;
    #pragma unroll
    for (int mt = 0; mt < 2; mt++) {
        int r0 = row0 + wr * 32 + mt * 16 + g;
        #pragma unroll
        for (int nt = 0; nt < 4; nt++) {
            int col = wc * 32 + nt * 8 + tg * 2;
            if (col < CC) {
                float b0 = bp[col], b1 = bp[col + 1];
                if (r0 < nrows)
                    *(float2*)(out + (size_t)r0 * CC + col) =
                        make_float2(c[mt][nt][0] + b0, c[mt][nt][1] + b1);
                if (r0 + 8 < nrows)
                    *(float2*)(out + (size_t)(r0 + 8) * CC + col) =
                        make_float2(c[mt][nt][2] + b0, c[mt][nt][3] + b1);
            }
        }
    }
}

// ---------------- launch ----------------
extern "C" void kernel_launch(void* const* d_in, const int* in_sizes, int n_in,
                              void* d_out, int out_size) {
    const float* x      = (const float*)d_in[0];
    const int*   ei     = (const int*)  d_in[1];
    const float* Wconv  = (const float*)d_in[2];
    const float* bconv  = (const float*)d_in[3];
    const float* Wlin   = (const float*)d_in[4];
    const float* blin   = (const float*)d_in[5];
    const float* ln_g   = (const float*)d_in[6];
    const float* ln_b   = (const float*)d_in[7];
    const float* Wpred  = (const float*)d_in[8];
    const float* bpred  = (const float*)d_in[9];
    float* out = (float*)d_out;

    int n = in_sizes[0] / DD;     // 50000
    int e = in_sizes[1] / 2;      // 600000

    static bool attr_set = false;
    if (!attr_set) {
        cudaFuncSetAttribute(k_mma, cudaFuncAttributeMaxDynamicSharedMemorySize,
                             MMA_SMEM);
        cudaFuncSetAttribute(k_predmma, cudaFuncAttributeMaxDynamicSharedMemorySize,
                             PRED_SMEM);
        attr_set = true;
    }

    int nb = (n + 1023) / 1024;

    k_deg  <<<(e + 255) / 256, 256>>>(ei, e);
    k_scan1<<<nb, 1024>>>(n);
    k_scan3<<<nb, 1024>>>(n, e);
    k_place<<<(e + 255) / 256, 256>>>(ei, e);
    k_prep <<<(NWTOT + NPAD * 32 + 255) / 256, 256>>>(Wconv, Wlin, Wpred, x, n);

    int ntiles = (n + 127) / 128;
    for (int i = 0; i < LL; i++) {
        k_mma<<<ntiles, 512, MMA_SMEM>>>(i, n);
        k_agg<<<(n + 7) / 8, 256>>>(bconv + i * HH, blin + i * HH,
                                    ln_g + i * HH, ln_b + i * HH, i, n);
    }

    k_predmma<<<ntiles, 256, PRED_SMEM>>>(bpred, out, n);
}